// round 10
// baseline (speedup 1.0000x reference)
#include <cuda_runtime.h>
#include <cuda_bf16.h>
#include <mma.h>
#include <math.h>

using namespace nvcuda;

// Problem constants (fixed by the bench)
#define BATCH 8
#define CIN   64
#define COUT  64
#define NPT   2048
#define DTOT  192           // 3*Cin feature dim for kNN
#define KNN   11            // k+1
#define NPAIR (BATCH*NPT)   // 16384 points total
#define NEDGE (BATCH*NPT*KNN)
#define TCAND 16            // candidates kept per row before exact refine
#define CCAP  320           // per-row candidate collection capacity

#define VN_EPS 1e-6f
#define BN_EPS 1e-5f

// ---------------- scratch (device globals; no cudaMalloc allowed) ----------------
__device__ float          g_pdist[(size_t)NPT * NPT];           // 16.8 MB, reused per batch (L2-resident)
__device__ float          g_rtm[(size_t)NPAIR * 16];            // per-row per-128-tile max
__device__ float          g_xt[(size_t)NPAIR * DTOT];           // transposed x: [bm][d]
__device__ __nv_bfloat16  g_hi[(size_t)NPAIR * DTOT];           // bf16 of xt
__device__ double         g_xx64[NPAIR];
__device__ __nv_bfloat16  g_hx[NPAIR];                          // bf16 hi of -0.5*xx
__device__ __nv_bfloat16  g_lx[NPAIR];                          // bf16 lo of -0.5*xx
__device__ int            g_cand[(size_t)NPAIR * TCAND];
__device__ int            g_idx[NEDGE];
__device__ float          g_yf[(size_t)NPAIR * DTOT];           // [bm][o*3+d]
__device__ float          g_yd[(size_t)NPAIR * DTOT];
__device__ float          g_nrm[(size_t)NPAIR * COUT];          // [bm][o]
__device__ float          g_dfd[(size_t)NPAIR * COUT];
__device__ float          g_dsq[(size_t)NPAIR * COUT];
__device__ float          g_v[(size_t)NPAIR * DTOT];            // per-point output vectors
__device__ int            g_cnt[NPAIR];
__device__ float          g_chA[COUT];
__device__ float          g_chB[COUT];

// ---------------- 0: transpose x -> g_xt [bm][d]; emit bf16 ----------------
__global__ void xt_kernel(const float* __restrict__ x) {
    __shared__ float t[32][33];
    int b  = blockIdx.z;
    int d0 = blockIdx.y * 32;
    int n0 = blockIdx.x * 32;
    const float* X = x + (size_t)b * DTOT * NPT;
    t[threadIdx.y][threadIdx.x] = X[(size_t)(d0 + threadIdx.y) * NPT + n0 + threadIdx.x];
    __syncthreads();
    float v = t[threadIdx.x][threadIdx.y];
    size_t o = ((size_t)(b << 11) + n0 + threadIdx.y) * DTOT + d0 + threadIdx.x;
    g_xt[o] = v;
    g_hi[o] = __float2bfloat16(v);
}

// ---------------- 1: xx in fp64 (exact) + bf16 hi/lo of -0.5*xx; zero counts ----------------
__global__ void xx64_kernel() {
    int p = blockIdx.x * blockDim.x + threadIdx.x;      // 16384 points
    const float* r = g_xt + (size_t)p * DTOT;
    double s = 0.0;
    #pragma unroll 8
    for (int d = 0; d < DTOT; d++) { double v = (double)r[d]; s += v * v; }
    g_xx64[p] = s;
    float m05 = (float)(-0.5 * s);
    __nv_bfloat16 hx = __float2bfloat16(m05);
    g_hx[p] = hx;
    g_lx[p] = __float2bfloat16(m05 - __bfloat162float(hx));
    g_cnt[p] = 0;
}

// ---------------- 2: tensor-core rank-score GEMM (per batch) + per-row tile max ----------------
// score[n][m] = x_n.x_m - 0.5*xx_m   (per-row-monotone transform of pdist)
#define SMLD 40   // smem row stride (bf16 elems), pad 8 to kill conflicts
__global__ __launch_bounds__(256) void knn_wmma(int bb) {
    int n0 = blockIdx.y * 128;
    int m0 = blockIdx.x * 128;

    __shared__ __nv_bfloat16 sA[2][128][SMLD];
    __shared__ __nv_bfloat16 sB[2][128][SMLD];

    int tid  = threadIdx.x;
    int warp = tid >> 5;
    int wm   = warp & 1;    // 2 warps along rows (n)
    int wn   = warp >> 1;   // 4 warps along cols (m)

    // per-thread load slots: (row0, c8) and (row0+64, c8)
    int row0 = tid >> 2;
    int c8   = (tid & 3) * 8;

    wmma::fragment<wmma::accumulator, 16, 16, 16, float> cf[4][2];
    #pragma unroll
    for (int i = 0; i < 4; i++)
        #pragma unroll
        for (int j = 0; j < 2; j++) wmma::fill_fragment(cf[i][j], 0.0f);

    // prologue: chunk 0 into buffer 0
    *(int4*)&sA[0][row0][c8]      = *(const int4*)&g_hi[(size_t)(bb + n0 + row0) * DTOT + c8];
    *(int4*)&sA[0][row0 + 64][c8] = *(const int4*)&g_hi[(size_t)(bb + n0 + row0 + 64) * DTOT + c8];
    *(int4*)&sB[0][row0][c8]      = *(const int4*)&g_hi[(size_t)(bb + m0 + row0) * DTOT + c8];
    *(int4*)&sB[0][row0 + 64][c8] = *(const int4*)&g_hi[(size_t)(bb + m0 + row0 + 64) * DTOT + c8];
    __syncthreads();

    // 6 chunks of BK=32 over K=192, double-buffered: [ldg next | compute cur | sts next | sync]
    for (int t = 0; t < 6; t++) {
        int4 na0, na1, nb0, nb1;
        if (t < 5) {
            int dof = (t + 1) * 32;
            na0 = *(const int4*)&g_hi[(size_t)(bb + n0 + row0) * DTOT + dof + c8];
            na1 = *(const int4*)&g_hi[(size_t)(bb + n0 + row0 + 64) * DTOT + dof + c8];
            nb0 = *(const int4*)&g_hi[(size_t)(bb + m0 + row0) * DTOT + dof + c8];
            nb1 = *(const int4*)&g_hi[(size_t)(bb + m0 + row0 + 64) * DTOT + dof + c8];
        }
        int cur = t & 1;
        #pragma unroll
        for (int kk = 0; kk < 32; kk += 16) {
            wmma::fragment<wmma::matrix_a, 16, 16, 16, __nv_bfloat16, wmma::row_major> af[4];
            wmma::fragment<wmma::matrix_b, 16, 16, 16, __nv_bfloat16, wmma::col_major> bfr[2];
            #pragma unroll
            for (int i = 0; i < 4; i++)
                wmma::load_matrix_sync(af[i], &sA[cur][wm * 64 + i * 16][kk], SMLD);
            #pragma unroll
            for (int j = 0; j < 2; j++)
                wmma::load_matrix_sync(bfr[j], &sB[cur][wn * 32 + j * 16][kk], SMLD);
            #pragma unroll
            for (int i = 0; i < 4; i++)
                #pragma unroll
                for (int j = 0; j < 2; j++)
                    wmma::mma_sync(cf[i][j], af[i], bfr[j], cf[i][j]);
        }
        if (t < 5) {
            int nxt = cur ^ 1;
            *(int4*)&sA[nxt][row0][c8]      = na0;
            *(int4*)&sA[nxt][row0 + 64][c8] = na1;
            *(int4*)&sB[nxt][row0][c8]      = nb0;
            *(int4*)&sB[nxt][row0 + 64][c8] = nb1;
        }
        __syncthreads();
    }

    // augmented tail k16: A=[1,1,0..], B=[hx_m,lx_m,0..]  -> adds -0.5*xx_m
    {
        const __nv_bfloat16 one = __float2bfloat16(1.0f);
        const __nv_bfloat16 zero = __float2bfloat16(0.0f);
        if (tid < 128) {
            int row = tid;
            sA[0][row][0] = one; sA[0][row][1] = one;
            #pragma unroll
            for (int c = 2; c < 16; c++) sA[0][row][c] = zero;
        } else {
            int row = tid - 128;
            sB[0][row][0] = g_hx[bb + m0 + row];
            sB[0][row][1] = g_lx[bb + m0 + row];
            #pragma unroll
            for (int c = 2; c < 16; c++) sB[0][row][c] = zero;
        }
        __syncthreads();
        wmma::fragment<wmma::matrix_a, 16, 16, 16, __nv_bfloat16, wmma::row_major> af[4];
        wmma::fragment<wmma::matrix_b, 16, 16, 16, __nv_bfloat16, wmma::col_major> bfr[2];
        #pragma unroll
        for (int i = 0; i < 4; i++)
            wmma::load_matrix_sync(af[i], &sA[0][wm * 64 + i * 16][0], SMLD);
        #pragma unroll
        for (int j = 0; j < 2; j++)
            wmma::load_matrix_sync(bfr[j], &sB[0][wn * 32 + j * 16][0], SMLD);
        #pragma unroll
        for (int i = 0; i < 4; i++)
            #pragma unroll
            for (int j = 0; j < 2; j++)
                wmma::mma_sync(cf[i][j], af[i], bfr[j], cf[i][j]);
    }

    // store raw scores (per-batch buffer, row index local)
    #pragma unroll
    for (int i = 0; i < 4; i++)
        #pragma unroll
        for (int j = 0; j < 2; j++) {
            float* op = g_pdist + ((size_t)(n0 + wm * 64 + i * 16)) * NPT
                        + m0 + wn * 32 + j * 16;
            wmma::store_matrix_sync(op, cf[i][j], NPT, wmma::mem_row_major);
        }

    // per-row max of this 128x128 tile (reads back own stores; block-visible after sync)
    __syncthreads();
    {
        float* smax = (float*)&sA[0][0][0];       // reuse smem
        int row  = tid >> 1;
        int half = tid & 1;
        const float4* p = (const float4*)(g_pdist + (size_t)(n0 + row) * NPT + m0 + half * 64);
        float mx = -INFINITY;
        #pragma unroll
        for (int j = 0; j < 16; j++) {
            float4 v = p[j];
            mx = fmaxf(mx, fmaxf(fmaxf(v.x, v.y), fmaxf(v.z, v.w)));
        }
        smax[row * 2 + half] = mx;
        __syncthreads();
        if (tid < 128)
            g_rtm[(size_t)(bb + n0 + tid) * 16 + blockIdx.x] = fmaxf(smax[tid * 2], smax[tid * 2 + 1]);
    }
}

// ---------------- 3: threshold-collect top-TCAND per row (warp per row, per batch) ----------------
__global__ __launch_bounds__(256) void cand_kernel(int bb) {
    int lrow  = (blockIdx.x * blockDim.x + threadIdx.x) >> 5;   // local row [0,2048)
    int lane  = threadIdx.x & 31;
    int wl    = threadIdx.x >> 5;
    int gwarp = bb + lrow;

    __shared__ float s_v[8][CCAP];
    __shared__ int   s_i[8][CCAP];

    // tau = min of the 16 tile maxima  (guarantees >=16 elements >= tau)
    float tm = (lane < 16) ? g_rtm[(size_t)gwarp * 16 + lane] : INFINITY;
    #pragma unroll
    for (int off = 8; off; off >>= 1) tm = fminf(tm, __shfl_down_sync(0xffffffff, tm, off));
    float tau = __shfl_sync(0xffffffff, tm, 0);

    const float4* row4 = (const float4*)(g_pdist + (size_t)lrow * NPT);
    int base = 0;
    #pragma unroll 2
    for (int i = 0; i < NPT / 128; i++) {
        int q = i * 32 + lane;
        float4 v = row4[q];
        float mx = fmaxf(fmaxf(v.x, v.y), fmaxf(v.z, v.w));
        unsigned any = __ballot_sync(0xffffffff, mx >= tau);
        if (any) {
            float vals[4] = {v.x, v.y, v.z, v.w};
            #pragma unroll
            for (int c = 0; c < 4; c++) {
                bool hit = vals[c] >= tau;
                unsigned m = __ballot_sync(0xffffffff, hit);
                if (m) {
                    if (hit) {
                        int pos = base + __popc(m & ((1u << lane) - 1));
                        if (pos < CCAP) { s_v[wl][pos] = vals[c]; s_i[wl][pos] = q * 4 + c; }
                    }
                    base += __popc(m);
                }
            }
        }
    }
    int cnt = min(base, CCAP);
    __syncwarp();

    // top-TCAND of collected (value desc, index asc)
    int* out = g_cand + (size_t)gwarp * TCAND;
    for (int r = 0; r < TCAND; r++) {
        float bv = -INFINITY; int bi = 0x7fffffff;
        for (int t = lane; t < cnt; t += 32) {
            float vv = s_v[wl][t]; int ii = s_i[wl][t];
            if (vv > bv || (vv == bv && ii < bi)) { bv = vv; bi = ii; }
        }
        #pragma unroll
        for (int off = 16; off; off >>= 1) {
            float ov = __shfl_down_sync(0xffffffff, bv, off);
            int   oi = __shfl_down_sync(0xffffffff, bi, off);
            if (ov > bv || (ov == bv && oi < bi)) { bv = ov; bi = oi; }
        }
        bv = __shfl_sync(0xffffffff, bv, 0);
        bi = __shfl_sync(0xffffffff, bi, 0);
        if (lane == 0) out[r] = bi;
        for (int t = lane; t < cnt; t += 32)
            if (s_i[wl][t] == bi) s_v[wl][t] = -INFINITY;
        __syncwarp();
    }
}

// ---------------- 4: compensated-fp32 (Dot2) refine -> final top-KNN (+ fused counts) ----------------
__global__ __launch_bounds__(256) void refine_kernel() {
    int row  = (blockIdx.x * blockDim.x + threadIdx.x) >> 5;  // [0,16384)
    int lane = threadIdx.x & 31;
    int wl   = threadIdx.x >> 5;
    int b    = row >> 11;

    __shared__ float s_val[8][TCAND];
    __shared__ int   s_id[8][TCAND];

    float xn[6];
    #pragma unroll
    for (int u = 0; u < 6; u++) xn[u] = g_xt[(size_t)row * DTOT + lane + 32 * u];
    float xxn = (float)g_xx64[row];

    for (int j = 0; j < TCAND; j++) {
        int m = g_cand[(size_t)row * TCAND + j];
        const float* xm = g_xt + ((size_t)(b << 11) + m) * DTOT;
        float s = 0.0f, comp = 0.0f;
        #pragma unroll
        for (int u = 0; u < 6; u++) {
            float a = xn[u], bv = xm[lane + 32 * u];
            float p  = __fmul_rn(a, bv);
            float pe = __fmaf_rn(a, bv, -p);              // exact product error
            float t  = __fadd_rn(s, p);                   // Knuth TwoSum
            float z  = __fsub_rn(t, s);
            float e  = __fadd_rn(__fsub_rn(s, __fsub_rn(t, z)), __fsub_rn(p, z));
            s = t;
            comp = __fadd_rn(comp, __fadd_rn(e, pe));
        }
        #pragma unroll
        for (int off = 16; off; off >>= 1) {
            float os = __shfl_down_sync(0xffffffff, s,    off);
            float oc = __shfl_down_sync(0xffffffff, comp, off);
            float t  = __fadd_rn(s, os);
            float z  = __fsub_rn(t, s);
            float e  = __fadd_rn(__fsub_rn(s, __fsub_rn(t, z)), __fsub_rn(os, z));
            s = t;
            comp = __fadd_rn(comp, __fadd_rn(e, oc));
        }
        if (lane == 0) {
            // emulate reference's fp32 expression structure for tie alignment:
            float innerf = __fadd_rn(s, comp);
            float pf = 2.0f * innerf;
            pf = pf - xxn;
            pf = pf - (float)g_xx64[(size_t)(b << 11) + m];
            s_val[wl][j] = pf;
            s_id[wl][j]  = m;
        }
    }
    __syncwarp();

    if (lane == 0) {
        int* out = g_idx + (size_t)row * KNN;
        int bb = (row >> 11) << 11;
        for (int r = 0; r < KNN; r++) {
            float bv = -INFINITY; int bi = 0x7fffffff; int bs = 0;
            #pragma unroll
            for (int t = 0; t < TCAND; t++) {
                float v = s_val[wl][t]; int id = s_id[wl][t];
                if (v > bv || (v == bv && id < bi)) { bv = v; bi = id; bs = t; }
            }
            out[r] = bi;
            atomicAdd(&g_cnt[bb + bi], 1);
            s_val[wl][bs] = -INFINITY;
        }
    }
}

// ---------------- 5: y_feat / y_dir  [bm][od] ----------------
__global__ void feat_kernel(const float* __restrict__ x,
                            const float* __restrict__ Wf,
                            const float* __restrict__ Wd) {
    __shared__ float wfs[64][64];   // [c][o]
    __shared__ float wds[64][64];
    __shared__ float xs[DTOT][16];

    int b = blockIdx.y;
    int n0 = blockIdx.x * 16;
    int tid = threadIdx.x;          // 192

    for (int i = tid; i < 4096; i += 192) {
        int o = i >> 6, c = i & 63;
        wfs[c][o] = Wf[i];
        wds[c][o] = Wd[i];
    }
    const float* X = x + (size_t)b * DTOT * NPT;
    for (int i = tid; i < DTOT * 16; i += 192) {
        int c3 = i >> 4, n = i & 15;
        xs[c3][n] = X[(size_t)c3 * NPT + n0 + n];
    }
    __syncthreads();

    int o = tid / 3;
    int d = tid - 3 * o;

    float af[16], ad_[16];
    #pragma unroll
    for (int n = 0; n < 16; n++) { af[n] = 0.f; ad_[n] = 0.f; }

    for (int c = 0; c < 64; c++) {
        float wf = wfs[c][o], wd = wds[c][o];
        #pragma unroll
        for (int n = 0; n < 16; n++) {
            float xv = xs[c * 3 + d][n];
            af[n]  = fmaf(wf, xv, af[n]);
            ad_[n] = fmaf(wd, xv, ad_[n]);
        }
    }
    #pragma unroll
    for (int n = 0; n < 16; n++) {
        size_t base = ((size_t)b * NPT + n0 + n) * DTOT + tid;
        g_yf[base] = af[n];
        g_yd[base] = ad_[n];
    }
}

// ---------------- 6: per-point norm / f·d / |d|^2 ----------------
__global__ void pstat_kernel() {
    int t = blockIdx.x * blockDim.x + threadIdx.x;  // 16384*64
    int bm = t >> 6;
    int o  = t & 63;
    const float* f = g_yf + (size_t)bm * DTOT + o * 3;
    const float* g = g_yd + (size_t)bm * DTOT + o * 3;
    float f0 = f[0], f1 = f[1], f2 = f[2];
    float g0 = g[0], g1 = g[1], g2 = g[2];
    g_nrm[t] = sqrtf(f0 * f0 + f1 * f1 + f2 * f2);
    g_dfd[t] = f0 * g0 + f1 * g1 + f2 * g2;
    g_dsq[t] = g0 * g0 + g1 * g1 + g2 * g2;
}

// ---------------- 8: BN stats (count-weighted, exact) ----------------
__global__ void bnstat_kernel(const float* __restrict__ gamma, const float* __restrict__ beta) {
    int o = blockIdx.x;
    int tid = threadIdx.x;  // 256
    double s1 = 0.0, s2 = 0.0;
    for (int bm = tid; bm < NPAIR; bm += 256) {
        float v = g_nrm[(size_t)bm * COUT + o];
        double c = (double)g_cnt[bm];
        s1 += c * v;
        s2 += c * (double)v * (double)v;
    }
    __shared__ double r1[256], r2[256];
    r1[tid] = s1; r2[tid] = s2;
    __syncthreads();
    for (int s = 128; s; s >>= 1) {
        if (tid < s) { r1[tid] += r1[tid + s]; r2[tid] += r2[tid + s]; }
        __syncthreads();
    }
    if (tid == 0) {
        const double cnt = (double)NEDGE;
        double mean = r1[0] / cnt;
        double var  = r2[0] / cnt - mean * mean;
        double a = (double)gamma[o] / sqrt(var + (double)BN_EPS);
        g_chA[o] = (float)a;
        g_chB[o] = (float)((double)beta[o] - mean * a);
    }
}

// ---------------- 9: per-point output vectors v ----------------
__global__ void v_kernel() {
    int bm = blockIdx.x;
    int od = threadIdx.x;       // 192
    int o = od / 3;
    size_t t = (size_t)bm * DTOT + od;
    size_t s = (size_t)bm * COUT + o;
    float n    = g_nrm[s];
    float scale = g_chA[o] + g_chB[o] / n;     // norm_bn / norm
    float dot  = scale * g_dfd[s];
    float pv   = scale * g_yf[t];
    float outv = pv;
    if (dot < 0.f) outv = pv - dot / (g_dsq[s] + VN_EPS) * g_yd[t];
    g_v[t] = outv;
}

// ---------------- 10: gather-mean to output ----------------
__global__ void gather_kernel(float* __restrict__ out) {
    __shared__ int sidx[16 * KNN];
    int b  = blockIdx.y;
    int n0 = blockIdx.x * 16;
    int tid = threadIdx.x;      // 192
    if (tid < 16 * KNN) sidx[tid] = g_idx[((size_t)b * NPT + n0) * KNN + tid];
    __syncthreads();

    const float* vb = g_v + (size_t)b * NPT * DTOT;
    float res[16];
    #pragma unroll
    for (int n = 0; n < 16; n++) {
        float acc = 0.f;
        #pragma unroll
        for (int k = 0; k < KNN; k++) {
            int m = sidx[n * KNN + k];
            acc += vb[(size_t)m * DTOT + tid];
        }
        res[n] = acc * (1.0f / (float)KNN);
    }
    float* ob = out + ((size_t)b * DTOT + tid) * NPT + n0;
    *(float4*)(ob)      = make_float4(res[0],  res[1],  res[2],  res[3]);
    *(float4*)(ob + 4)  = make_float4(res[4],  res[5],  res[6],  res[7]);
    *(float4*)(ob + 8)  = make_float4(res[8],  res[9],  res[10], res[11]);
    *(float4*)(ob + 12) = make_float4(res[12], res[13], res[14], res[15]);
}

// ---------------- launch ----------------
extern "C" void kernel_launch(void* const* d_in, const int* in_sizes, int n_in,
                              void* d_out, int out_size) {
    const float* x     = (const float*)d_in[0];
    const float* Wf    = (const float*)d_in[1];
    const float* Wd    = (const float*)d_in[2];
    const float* gamma = (const float*)d_in[3];
    const float* beta  = (const float*)d_in[4];
    float* out = (float*)d_out;

    xt_kernel<<<dim3(NPT / 32, DTOT / 32, BATCH), dim3(32, 32)>>>(x);
    xx64_kernel<<<NPAIR / 256, 256>>>();
    for (int b = 0; b < BATCH; b++) {
        knn_wmma<<<dim3(NPT / 128, NPT / 128), 256>>>(b << 11);
        cand_kernel<<<NPT / 8, 256>>>(b << 11);
    }
    refine_kernel<<<NPAIR / 8, 256>>>();
    feat_kernel<<<dim3(NPT / 16, BATCH), 192>>>(x, Wf, Wd);
    pstat_kernel<<<(NPAIR * COUT) / 256, 256>>>();
    bnstat_kernel<<<COUT, 256>>>(gamma, beta);
    v_kernel<<<NPAIR, DTOT>>>();
    gather_kernel<<<dim3(NPT / 16, BATCH), DTOT>>>(out);
}

// round 13
// speedup vs baseline: 1.3248x; 1.3248x over previous
#include <cuda_runtime.h>
#include <cuda_bf16.h>
#include <mma.h>
#include <math.h>

using namespace nvcuda;

// Problem constants (fixed by the bench)
#define BATCH 8
#define CIN   64
#define COUT  64
#define NPT   2048
#define DTOT  192           // 3*Cin feature dim for kNN
#define KNN   11            // k+1
#define NPAIR (BATCH*NPT)   // 16384 points total
#define NEDGE (BATCH*NPT*KNN)
#define TCAND 16            // candidates kept per row before exact refine
#define CCAP  320           // per-row candidate collection capacity
#define NGRP  64            // 32-col groups per row

#define VN_EPS 1e-6f
#define BN_EPS 1e-5f

// ---------------- scratch (device globals; no cudaMalloc allowed) ----------------
__device__ float          g_pdist[(size_t)BATCH * NPT * NPT];   // 134 MB (rank scores)
__device__ float          g_rtm[(size_t)NPAIR * NGRP];          // per-row per-32col-group max
__device__ float          g_xt[(size_t)NPAIR * DTOT];           // transposed x: [bm][d]
__device__ __nv_bfloat16  g_hi[(size_t)NPAIR * DTOT];           // bf16 of xt
__device__ double         g_xx64[NPAIR];
__device__ __nv_bfloat16  g_hx[NPAIR];                          // bf16 hi of -0.5*xx
__device__ __nv_bfloat16  g_lx[NPAIR];                          // bf16 lo of -0.5*xx
__device__ int            g_cand[(size_t)NPAIR * TCAND];
__device__ int            g_idx[NEDGE];
__device__ float          g_yf[(size_t)NPAIR * DTOT];           // [bm][o*3+d]
__device__ float          g_yd[(size_t)NPAIR * DTOT];
__device__ float          g_nrm[(size_t)NPAIR * COUT];          // [bm][o]
__device__ float          g_dfd[(size_t)NPAIR * COUT];
__device__ float          g_dsq[(size_t)NPAIR * COUT];
__device__ float          g_v[(size_t)NPAIR * DTOT];            // per-point output vectors
__device__ int            g_cnt[NPAIR];
__device__ float          g_chA[COUT];
__device__ float          g_chB[COUT];

// ---------------- 0: transpose x -> g_xt [bm][d]; emit bf16 ----------------
__global__ void xt_kernel(const float* __restrict__ x) {
    __shared__ float t[32][33];
    int b  = blockIdx.z;
    int d0 = blockIdx.y * 32;
    int n0 = blockIdx.x * 32;
    const float* X = x + (size_t)b * DTOT * NPT;
    t[threadIdx.y][threadIdx.x] = X[(size_t)(d0 + threadIdx.y) * NPT + n0 + threadIdx.x];
    __syncthreads();
    float v = t[threadIdx.x][threadIdx.y];
    size_t o = ((size_t)(b << 11) + n0 + threadIdx.y) * DTOT + d0 + threadIdx.x;
    g_xt[o] = v;
    g_hi[o] = __float2bfloat16(v);
}

// ---------------- 1: xx in fp64 (exact) + bf16 hi/lo of -0.5*xx; zero counts ----------------
__global__ void xx64_kernel() {
    int p = blockIdx.x * blockDim.x + threadIdx.x;      // 16384 points
    const float* r = g_xt + (size_t)p * DTOT;
    double s = 0.0;
    #pragma unroll 8
    for (int d = 0; d < DTOT; d++) { double v = (double)r[d]; s += v * v; }
    g_xx64[p] = s;
    float m05 = (float)(-0.5 * s);
    __nv_bfloat16 hx = __float2bfloat16(m05);
    g_hx[p] = hx;
    g_lx[p] = __float2bfloat16(m05 - __bfloat162float(hx));
    g_cnt[p] = 0;
}

// ---------------- 2: tensor-core rank-score GEMM + per-row 32-col-group max ----------------
// score[n][m] = x_n.x_m - 0.5*xx_m   (per-row-monotone transform of pdist)
#define SMLD 40   // smem row stride (bf16 elems), pad 8 to kill conflicts
__global__ __launch_bounds__(256) void knn_wmma() {
    int bb = blockIdx.z << 11;
    int n0 = blockIdx.y * 128;
    int m0 = blockIdx.x * 128;

    __shared__ __nv_bfloat16 sA[2][128][SMLD];
    __shared__ __nv_bfloat16 sB[2][128][SMLD];

    int tid  = threadIdx.x;
    int warp = tid >> 5;
    int wm   = warp & 1;    // 2 warps along rows (n)
    int wn   = warp >> 1;   // 4 warps along cols (m)

    int row0 = tid >> 2;
    int c8   = (tid & 3) * 8;

    wmma::fragment<wmma::accumulator, 16, 16, 16, float> cf[4][2];
    #pragma unroll
    for (int i = 0; i < 4; i++)
        #pragma unroll
        for (int j = 0; j < 2; j++) wmma::fill_fragment(cf[i][j], 0.0f);

    // prologue: chunk 0 into buffer 0
    *(int4*)&sA[0][row0][c8]      = *(const int4*)&g_hi[(size_t)(bb + n0 + row0) * DTOT + c8];
    *(int4*)&sA[0][row0 + 64][c8] = *(const int4*)&g_hi[(size_t)(bb + n0 + row0 + 64) * DTOT + c8];
    *(int4*)&sB[0][row0][c8]      = *(const int4*)&g_hi[(size_t)(bb + m0 + row0) * DTOT + c8];
    *(int4*)&sB[0][row0 + 64][c8] = *(const int4*)&g_hi[(size_t)(bb + m0 + row0 + 64) * DTOT + c8];
    __syncthreads();

    // 6 chunks of BK=32 over K=192, double-buffered: [ldg next | compute cur | sts next | sync]
    for (int t = 0; t < 6; t++) {
        int4 na0, na1, nb0, nb1;
        if (t < 5) {
            int dof = (t + 1) * 32;
            na0 = *(const int4*)&g_hi[(size_t)(bb + n0 + row0) * DTOT + dof + c8];
            na1 = *(const int4*)&g_hi[(size_t)(bb + n0 + row0 + 64) * DTOT + dof + c8];
            nb0 = *(const int4*)&g_hi[(size_t)(bb + m0 + row0) * DTOT + dof + c8];
            nb1 = *(const int4*)&g_hi[(size_t)(bb + m0 + row0 + 64) * DTOT + dof + c8];
        }
        int cur = t & 1;
        #pragma unroll
        for (int kk = 0; kk < 32; kk += 16) {
            wmma::fragment<wmma::matrix_a, 16, 16, 16, __nv_bfloat16, wmma::row_major> af[4];
            wmma::fragment<wmma::matrix_b, 16, 16, 16, __nv_bfloat16, wmma::col_major> bfr[2];
            #pragma unroll
            for (int i = 0; i < 4; i++)
                wmma::load_matrix_sync(af[i], &sA[cur][wm * 64 + i * 16][kk], SMLD);
            #pragma unroll
            for (int j = 0; j < 2; j++)
                wmma::load_matrix_sync(bfr[j], &sB[cur][wn * 32 + j * 16][kk], SMLD);
            #pragma unroll
            for (int i = 0; i < 4; i++)
                #pragma unroll
                for (int j = 0; j < 2; j++)
                    wmma::mma_sync(cf[i][j], af[i], bfr[j], cf[i][j]);
        }
        if (t < 5) {
            int nxt = cur ^ 1;
            *(int4*)&sA[nxt][row0][c8]      = na0;
            *(int4*)&sA[nxt][row0 + 64][c8] = na1;
            *(int4*)&sB[nxt][row0][c8]      = nb0;
            *(int4*)&sB[nxt][row0 + 64][c8] = nb1;
        }
        __syncthreads();
    }

    // augmented tail k16: A=[1,1,0..], B=[hx_m,lx_m,0..]  -> adds -0.5*xx_m
    {
        const __nv_bfloat16 one = __float2bfloat16(1.0f);
        const __nv_bfloat16 zero = __float2bfloat16(0.0f);
        if (tid < 128) {
            int row = tid;
            sA[0][row][0] = one; sA[0][row][1] = one;
            #pragma unroll
            for (int c = 2; c < 16; c++) sA[0][row][c] = zero;
        } else {
            int row = tid - 128;
            sB[0][row][0] = g_hx[bb + m0 + row];
            sB[0][row][1] = g_lx[bb + m0 + row];
            #pragma unroll
            for (int c = 2; c < 16; c++) sB[0][row][c] = zero;
        }
        __syncthreads();
        wmma::fragment<wmma::matrix_a, 16, 16, 16, __nv_bfloat16, wmma::row_major> af[4];
        wmma::fragment<wmma::matrix_b, 16, 16, 16, __nv_bfloat16, wmma::col_major> bfr[2];
        #pragma unroll
        for (int i = 0; i < 4; i++)
            wmma::load_matrix_sync(af[i], &sA[0][wm * 64 + i * 16][0], SMLD);
        #pragma unroll
        for (int j = 0; j < 2; j++)
            wmma::load_matrix_sync(bfr[j], &sB[0][wn * 32 + j * 16][0], SMLD);
        #pragma unroll
        for (int i = 0; i < 4; i++)
            #pragma unroll
            for (int j = 0; j < 2; j++)
                wmma::mma_sync(cf[i][j], af[i], bfr[j], cf[i][j]);
    }

    // store raw scores
    #pragma unroll
    for (int i = 0; i < 4; i++)
        #pragma unroll
        for (int j = 0; j < 2; j++) {
            float* op = g_pdist + ((size_t)(bb + n0 + wm * 64 + i * 16)) * NPT
                        + m0 + wn * 32 + j * 16;
            wmma::store_matrix_sync(op, cf[i][j], NPT, wmma::mem_row_major);
        }

    // per-row 32-col-group maxes (reads back own stores; block-visible after sync)
    __syncthreads();
    {
        int row  = tid >> 1;
        int half = tid & 1;
        const float4* p = (const float4*)(g_pdist + (size_t)(bb + n0 + row) * NPT + m0 + half * 64);
        float m0v = -INFINITY, m1v = -INFINITY;
        #pragma unroll
        for (int j = 0; j < 8; j++) {
            float4 v = p[j];
            m0v = fmaxf(m0v, fmaxf(fmaxf(v.x, v.y), fmaxf(v.z, v.w)));
        }
        #pragma unroll
        for (int j = 8; j < 16; j++) {
            float4 v = p[j];
            m1v = fmaxf(m1v, fmaxf(fmaxf(v.x, v.y), fmaxf(v.z, v.w)));
        }
        float* rt = g_rtm + (size_t)(bb + n0 + row) * NGRP + blockIdx.x * 4 + half * 2;
        rt[0] = m0v;
        rt[1] = m1v;
    }
}

// ---------------- 3: group-skip threshold-collect top-TCAND per row (warp per row) ----------------
__global__ __launch_bounds__(256) void cand_kernel() {
    int gwarp = (blockIdx.x * blockDim.x + threadIdx.x) >> 5;   // row id [0,16384)
    int lane  = threadIdx.x & 31;
    int wl    = threadIdx.x >> 5;

    __shared__ float s_v[8][CCAP];
    __shared__ int   s_i[8][CCAP];
    __shared__ int   s_g[8][NGRP];

    // load 64 group maxima (2 per lane)
    const float* rtm = g_rtm + (size_t)gwarp * NGRP;
    float gm0 = rtm[lane];
    float gm1 = rtm[lane + 32];

    // tau = 16th-largest of the 64 group maxima (guarantees >=16 elements >= tau,
    // and approx-top-16 of the row is contained in {v >= tau})
    float a0 = gm0, a1 = gm1, tau = 0.f;
    #pragma unroll
    for (int r = 0; r < 16; r++) {
        float mx = fmaxf(a0, a1);
        #pragma unroll
        for (int off = 16; off; off >>= 1) mx = fmaxf(mx, __shfl_xor_sync(0xffffffff, mx, off));
        tau = mx;
        unsigned msk = __ballot_sync(0xffffffff, a0 == mx || a1 == mx);
        int src = __ffs(msk) - 1;
        if (lane == src) { if (a0 == mx) a0 = -INFINITY; else a1 = -INFINITY; }
    }

    // compact list of selected groups (max >= tau)
    unsigned m0s = __ballot_sync(0xffffffff, gm0 >= tau);
    unsigned m1s = __ballot_sync(0xffffffff, gm1 >= tau);
    unsigned lt = (1u << lane) - 1;
    int n0s = __popc(m0s);
    if (gm0 >= tau) s_g[wl][__popc(m0s & lt)] = lane;
    if (gm1 >= tau) s_g[wl][n0s + __popc(m1s & lt)] = 32 + lane;
    int nsel = n0s + __popc(m1s);
    __syncwarp();

    // scan only selected groups: 4 groups per iteration (8 lanes per group, 1 float4 each)
    const float4* row4 = (const float4*)(g_pdist + (size_t)gwarp * NPT);
    int base = 0;
    for (int c = 0; c < nsel; c += 4) {
        int gi  = c + (lane >> 3);
        int sub = lane & 7;
        bool act = gi < nsel;
        int grp = act ? s_g[wl][gi] : 0;
        int q = grp * 8 + sub;
        float4 v = act ? row4[q] : make_float4(-INFINITY, -INFINITY, -INFINITY, -INFINITY);
        float vals[4] = {v.x, v.y, v.z, v.w};
        float mx = fmaxf(fmaxf(vals[0], vals[1]), fmaxf(vals[2], vals[3]));
        unsigned any = __ballot_sync(0xffffffff, mx >= tau);
        if (any) {
            #pragma unroll
            for (int e = 0; e < 4; e++) {
                bool hit = vals[e] >= tau;
                unsigned m = __ballot_sync(0xffffffff, hit);
                if (m) {
                    if (hit) {
                        int pos = base + __popc(m & lt);
                        if (pos < CCAP) { s_v[wl][pos] = vals[e]; s_i[wl][pos] = q * 4 + e; }
                    }
                    base += __popc(m);
                }
            }
        }
    }
    int cnt = min(base, CCAP);
    __syncwarp();

    // top-TCAND of collected (value desc, index asc)
    int* out = g_cand + (size_t)gwarp * TCAND;
    for (int r = 0; r < TCAND; r++) {
        float bv = -INFINITY; int bi = 0x7fffffff;
        for (int t = lane; t < cnt; t += 32) {
            float vv = s_v[wl][t]; int ii = s_i[wl][t];
            if (vv > bv || (vv == bv && ii < bi)) { bv = vv; bi = ii; }
        }
        #pragma unroll
        for (int off = 16; off; off >>= 1) {
            float ov = __shfl_down_sync(0xffffffff, bv, off);
            int   oi = __shfl_down_sync(0xffffffff, bi, off);
            if (ov > bv || (ov == bv && oi < bi)) { bv = ov; bi = oi; }
        }
        bv = __shfl_sync(0xffffffff, bv, 0);
        bi = __shfl_sync(0xffffffff, bi, 0);
        if (lane == 0) out[r] = bi;
        for (int t = lane; t < cnt; t += 32)
            if (s_i[wl][t] == bi) s_v[wl][t] = -INFINITY;
        __syncwarp();
    }
}

// ---------------- 4: compensated-fp32 (Dot2) refine -> final top-KNN (+ fused counts) ----------------
__global__ __launch_bounds__(256) void refine_kernel() {
    int row  = (blockIdx.x * blockDim.x + threadIdx.x) >> 5;  // [0,16384)
    int lane = threadIdx.x & 31;
    int wl   = threadIdx.x >> 5;
    int b    = row >> 11;

    __shared__ float s_val[8][TCAND];
    __shared__ int   s_id[8][TCAND];

    float xn[6];
    #pragma unroll
    for (int u = 0; u < 6; u++) xn[u] = g_xt[(size_t)row * DTOT + lane + 32 * u];
    float xxn = (float)g_xx64[row];

    for (int j = 0; j < TCAND; j++) {
        int m = g_cand[(size_t)row * TCAND + j];
        const float* xm = g_xt + ((size_t)(b << 11) + m) * DTOT;
        float s = 0.0f, comp = 0.0f;
        #pragma unroll
        for (int u = 0; u < 6; u++) {
            float a = xn[u], bv = xm[lane + 32 * u];
            float p  = __fmul_rn(a, bv);
            float pe = __fmaf_rn(a, bv, -p);              // exact product error
            float t  = __fadd_rn(s, p);                   // Knuth TwoSum
            float z  = __fsub_rn(t, s);
            float e  = __fadd_rn(__fsub_rn(s, __fsub_rn(t, z)), __fsub_rn(p, z));
            s = t;
            comp = __fadd_rn(comp, __fadd_rn(e, pe));
        }
        #pragma unroll
        for (int off = 16; off; off >>= 1) {
            float os = __shfl_down_sync(0xffffffff, s,    off);
            float oc = __shfl_down_sync(0xffffffff, comp, off);
            float t  = __fadd_rn(s, os);
            float z  = __fsub_rn(t, s);
            float e  = __fadd_rn(__fsub_rn(s, __fsub_rn(t, z)), __fsub_rn(os, z));
            s = t;
            comp = __fadd_rn(comp, __fadd_rn(e, oc));
        }
        if (lane == 0) {
            // emulate reference's fp32 expression structure for tie alignment:
            float innerf = __fadd_rn(s, comp);
            float pf = 2.0f * innerf;
            pf = pf - xxn;
            pf = pf - (float)g_xx64[(size_t)(b << 11) + m];
            s_val[wl][j] = pf;
            s_id[wl][j]  = m;
        }
    }
    __syncwarp();

    if (lane == 0) {
        int* out = g_idx + (size_t)row * KNN;
        int bb = (row >> 11) << 11;
        for (int r = 0; r < KNN; r++) {
            float bv = -INFINITY; int bi = 0x7fffffff; int bs = 0;
            #pragma unroll
            for (int t = 0; t < TCAND; t++) {
                float v = s_val[wl][t]; int id = s_id[wl][t];
                if (v > bv || (v == bv && id < bi)) { bv = v; bi = id; bs = t; }
            }
            out[r] = bi;
            atomicAdd(&g_cnt[bb + bi], 1);
            s_val[wl][bs] = -INFINITY;
        }
    }
}

// ---------------- 5: y_feat / y_dir  [bm][od] ----------------
__global__ void feat_kernel(const float* __restrict__ x,
                            const float* __restrict__ Wf,
                            const float* __restrict__ Wd) {
    __shared__ float wfs[64][64];   // [c][o]
    __shared__ float wds[64][64];
    __shared__ float xs[DTOT][16];

    int b = blockIdx.y;
    int n0 = blockIdx.x * 16;
    int tid = threadIdx.x;          // 192

    for (int i = tid; i < 4096; i += 192) {
        int o = i >> 6, c = i & 63;
        wfs[c][o] = Wf[i];
        wds[c][o] = Wd[i];
    }
    const float* X = x + (size_t)b * DTOT * NPT;
    for (int i = tid; i < DTOT * 16; i += 192) {
        int c3 = i >> 4, n = i & 15;
        xs[c3][n] = X[(size_t)c3 * NPT + n0 + n];
    }
    __syncthreads();

    int o = tid / 3;
    int d = tid - 3 * o;

    float af[16], ad_[16];
    #pragma unroll
    for (int n = 0; n < 16; n++) { af[n] = 0.f; ad_[n] = 0.f; }

    for (int c = 0; c < 64; c++) {
        float wf = wfs[c][o], wd = wds[c][o];
        #pragma unroll
        for (int n = 0; n < 16; n++) {
            float xv = xs[c * 3 + d][n];
            af[n]  = fmaf(wf, xv, af[n]);
            ad_[n] = fmaf(wd, xv, ad_[n]);
        }
    }
    #pragma unroll
    for (int n = 0; n < 16; n++) {
        size_t base = ((size_t)b * NPT + n0 + n) * DTOT + tid;
        g_yf[base] = af[n];
        g_yd[base] = ad_[n];
    }
}

// ---------------- 6: per-point norm / f·d / |d|^2 ----------------
__global__ void pstat_kernel() {
    int t = blockIdx.x * blockDim.x + threadIdx.x;  // 16384*64
    int bm = t >> 6;
    int o  = t & 63;
    const float* f = g_yf + (size_t)bm * DTOT + o * 3;
    const float* g = g_yd + (size_t)bm * DTOT + o * 3;
    float f0 = f[0], f1 = f[1], f2 = f[2];
    float g0 = g[0], g1 = g[1], g2 = g[2];
    g_nrm[t] = sqrtf(f0 * f0 + f1 * f1 + f2 * f2);
    g_dfd[t] = f0 * g0 + f1 * g1 + f2 * g2;
    g_dsq[t] = g0 * g0 + g1 * g1 + g2 * g2;
}

// ---------------- 8: BN stats (count-weighted, exact) ----------------
__global__ void bnstat_kernel(const float* __restrict__ gamma, const float* __restrict__ beta) {
    int o = blockIdx.x;
    int tid = threadIdx.x;  // 256
    double s1 = 0.0, s2 = 0.0;
    for (int bm = tid; bm < NPAIR; bm += 256) {
        float v = g_nrm[(size_t)bm * COUT + o];
        double c = (double)g_cnt[bm];
        s1 += c * v;
        s2 += c * (double)v * (double)v;
    }
    __shared__ double r1[256], r2[256];
    r1[tid] = s1; r2[tid] = s2;
    __syncthreads();
    for (int s = 128; s; s >>= 1) {
        if (tid < s) { r1[tid] += r1[tid + s]; r2[tid] += r2[tid + s]; }
        __syncthreads();
    }
    if (tid == 0) {
        const double cnt = (double)NEDGE;
        double mean = r1[0] / cnt;
        double var  = r2[0] / cnt - mean * mean;
        double a = (double)gamma[o] / sqrt(var + (double)BN_EPS);
        g_chA[o] = (float)a;
        g_chB[o] = (float)((double)beta[o] - mean * a);
    }
}

// ---------------- 9: per-point output vectors v ----------------
__global__ void v_kernel() {
    int bm = blockIdx.x;
    int od = threadIdx.x;       // 192
    int o = od / 3;
    size_t t = (size_t)bm * DTOT + od;
    size_t s = (size_t)bm * COUT + o;
    float n    = g_nrm[s];
    float scale = g_chA[o] + g_chB[o] / n;     // norm_bn / norm
    float dot  = scale * g_dfd[s];
    float pv   = scale * g_yf[t];
    float outv = pv;
    if (dot < 0.f) outv = pv - dot / (g_dsq[s] + VN_EPS) * g_yd[t];
    g_v[t] = outv;
}

// ---------------- 10: gather-mean to output ----------------
__global__ void gather_kernel(float* __restrict__ out) {
    __shared__ int sidx[16 * KNN];
    int b  = blockIdx.y;
    int n0 = blockIdx.x * 16;
    int tid = threadIdx.x;      // 192
    if (tid < 16 * KNN) sidx[tid] = g_idx[((size_t)b * NPT + n0) * KNN + tid];
    __syncthreads();

    const float* vb = g_v + (size_t)b * NPT * DTOT;
    float res[16];
    #pragma unroll
    for (int n = 0; n < 16; n++) {
        float acc = 0.f;
        #pragma unroll
        for (int k = 0; k < KNN; k++) {
            int m = sidx[n * KNN + k];
            acc += vb[(size_t)m * DTOT + tid];
        }
        res[n] = acc * (1.0f / (float)KNN);
    }
    float* ob = out + ((size_t)b * DTOT + tid) * NPT + n0;
    *(float4*)(ob)      = make_float4(res[0],  res[1],  res[2],  res[3]);
    *(float4*)(ob + 4)  = make_float4(res[4],  res[5],  res[6],  res[7]);
    *(float4*)(ob + 8)  = make_float4(res[8],  res[9],  res[10], res[11]);
    *(float4*)(ob + 12) = make_float4(res[12], res[13], res[14], res[15]);
}

// ---------------- launch ----------------
extern "C" void kernel_launch(void* const* d_in, const int* in_sizes, int n_in,
                              void* d_out, int out_size) {
    const float* x     = (const float*)d_in[0];
    const float* Wf    = (const float*)d_in[1];
    const float* Wd    = (const float*)d_in[2];
    const float* gamma = (const float*)d_in[3];
    const float* beta  = (const float*)d_in[4];
    float* out = (float*)d_out;

    xt_kernel<<<dim3(NPT / 32, DTOT / 32, BATCH), dim3(32, 32)>>>(x);
    xx64_kernel<<<NPAIR / 256, 256>>>();
    knn_wmma<<<dim3(NPT / 128, NPT / 128, BATCH), 256>>>();
    cand_kernel<<<NPAIR / 8, 256>>>();
    refine_kernel<<<NPAIR / 8, 256>>>();
    feat_kernel<<<dim3(NPT / 16, BATCH), 192>>>(x, Wf, Wd);
    pstat_kernel<<<(NPAIR * COUT) / 256, 256>>>();
    bnstat_kernel<<<COUT, 256>>>(gamma, beta);
    v_kernel<<<NPAIR, DTOT>>>();
    gather_kernel<<<dim3(NPT / 16, BATCH), DTOT>>>(out);
}

// round 15
// speedup vs baseline: 1.3321x; 1.0055x over previous
#include <cuda_runtime.h>
#include <cuda_bf16.h>
#include <mma.h>
#include <math.h>
#include <stdint.h>

using namespace nvcuda;

// Problem constants (fixed by the bench)
#define BATCH 8
#define CIN   64
#define COUT  64
#define NPT   2048
#define DTOT  192           // 3*Cin feature dim for kNN
#define KNN   11            // k+1
#define NPAIR (BATCH*NPT)   // 16384 points total
#define NEDGE (BATCH*NPT*KNN)
#define TCAND 16            // candidates kept per row before exact refine
#define CCAP  320           // per-row candidate collection capacity
#define NGRP  64            // 32-col groups per row

#define VN_EPS 1e-6f
#define BN_EPS 1e-5f

// ---------------- scratch (device globals; no cudaMalloc allowed) ----------------
__device__ float          g_pdist[(size_t)BATCH * NPT * NPT];   // 134 MB (rank scores)
__device__ float          g_rtm[(size_t)NPAIR * NGRP];          // per-row per-32col-group max
__device__ float          g_xt[(size_t)NPAIR * DTOT];           // transposed x: [bm][d]
__device__ __nv_bfloat16  g_hi[(size_t)NPAIR * DTOT];           // bf16 of xt
__device__ double         g_xx64[NPAIR];
__device__ __nv_bfloat16  g_hx[NPAIR];                          // bf16 hi of -0.5*xx
__device__ __nv_bfloat16  g_lx[NPAIR];                          // bf16 lo of -0.5*xx
__device__ int            g_cand[(size_t)NPAIR * TCAND];
__device__ int            g_idx[NEDGE];
__device__ float          g_yf[(size_t)NPAIR * DTOT];           // [bm][o*3+d]
__device__ float          g_yd[(size_t)NPAIR * DTOT];
__device__ float          g_nrm[(size_t)NPAIR * COUT];          // [bm][o]
__device__ float          g_dfd[(size_t)NPAIR * COUT];
__device__ float          g_dsq[(size_t)NPAIR * COUT];
__device__ float          g_v[(size_t)NPAIR * DTOT];            // per-point output vectors
__device__ int            g_cnt[NPAIR];
__device__ float          g_chA[COUT];
__device__ float          g_chB[COUT];

// ---------------- cp.async helpers ----------------
__device__ __forceinline__ void cp16(void* s, const void* g) {
    unsigned int sa = (unsigned int)__cvta_generic_to_shared(s);
    asm volatile("cp.async.cg.shared.global [%0], [%1], 16;" :: "r"(sa), "l"(g));
}
#define CP_COMMIT() asm volatile("cp.async.commit_group;" ::: "memory")
#define CP_WAIT0()  asm volatile("cp.async.wait_group 0;" ::: "memory")

// ---------------- 0: transpose x -> g_xt [bm][d]; emit bf16 ----------------
__global__ void xt_kernel(const float* __restrict__ x) {
    __shared__ float t[32][33];
    int b  = blockIdx.z;
    int d0 = blockIdx.y * 32;
    int n0 = blockIdx.x * 32;
    const float* X = x + (size_t)b * DTOT * NPT;
    t[threadIdx.y][threadIdx.x] = X[(size_t)(d0 + threadIdx.y) * NPT + n0 + threadIdx.x];
    __syncthreads();
    float v = t[threadIdx.x][threadIdx.y];
    size_t o = ((size_t)(b << 11) + n0 + threadIdx.y) * DTOT + d0 + threadIdx.x;
    g_xt[o] = v;
    g_hi[o] = __float2bfloat16(v);
}

// ---------------- 1: xx in fp64 (exact) + bf16 hi/lo of -0.5*xx; zero counts ----------------
__global__ void xx64_kernel() {
    int p = blockIdx.x * blockDim.x + threadIdx.x;      // 16384 points
    const float* r = g_xt + (size_t)p * DTOT;
    double s = 0.0;
    #pragma unroll 8
    for (int d = 0; d < DTOT; d++) { double v = (double)r[d]; s += v * v; }
    g_xx64[p] = s;
    float m05 = (float)(-0.5 * s);
    __nv_bfloat16 hx = __float2bfloat16(m05);
    g_hx[p] = hx;
    g_lx[p] = __float2bfloat16(m05 - __bfloat162float(hx));
    g_cnt[p] = 0;
}

// ---------------- 2: tensor-core rank-score GEMM (128x256 tile, cp.async pipeline) ----------------
// score[n][m] = x_n.x_m - 0.5*xx_m   (per-row-monotone transform of pdist)
#define SMLD 40   // smem row stride (bf16 elems), pad 8 to kill conflicts
#define KNN_SMEM (2*128*SMLD*2 + 2*256*SMLD*2)   // 61440 B

__global__ __launch_bounds__(256) void knn_wmma() {
    extern __shared__ char dsm[];
    __nv_bfloat16 (*sA)[128][SMLD] = reinterpret_cast<__nv_bfloat16 (*)[128][SMLD]>(dsm);
    __nv_bfloat16 (*sB)[256][SMLD] = reinterpret_cast<__nv_bfloat16 (*)[256][SMLD]>(dsm + 2 * 128 * SMLD * 2);

    int bb = blockIdx.z << 11;
    int n0 = blockIdx.y * 128;
    int m0 = blockIdx.x * 256;

    int tid  = threadIdx.x;
    int warp = tid >> 5;
    int wm   = warp & 1;    // 2 warps along rows (n), 64 each
    int wn   = warp >> 1;   // 4 warps along cols (m), 64 each

    auto load_chunk = [&](int buf, int dof) {
        #pragma unroll
        for (int r = 0; r < 2; r++) {
            int s = tid + r * 256;          // 512 A slots
            int row = s >> 2, c8 = (s & 3) * 8;
            cp16(&sA[buf][row][c8], &g_hi[(size_t)(bb + n0 + row) * DTOT + dof + c8]);
        }
        #pragma unroll
        for (int r = 0; r < 4; r++) {
            int s = tid + r * 256;          // 1024 B slots
            int row = s >> 2, c8 = (s & 3) * 8;
            cp16(&sB[buf][row][c8], &g_hi[(size_t)(bb + m0 + row) * DTOT + dof + c8]);
        }
    };

    wmma::fragment<wmma::accumulator, 16, 16, 16, float> cf[4][4];
    #pragma unroll
    for (int i = 0; i < 4; i++)
        #pragma unroll
        for (int j = 0; j < 4; j++) wmma::fill_fragment(cf[i][j], 0.0f);

    // prologue
    load_chunk(0, 0);
    CP_COMMIT();
    CP_WAIT0();
    __syncthreads();

    // 6 chunks of BK=32 over K=192: [issue next via cp.async | compute cur | wait | sync]
    for (int t = 0; t < 6; t++) {
        if (t < 5) { load_chunk((t + 1) & 1, (t + 1) * 32); CP_COMMIT(); }
        int cur = t & 1;
        #pragma unroll
        for (int kk = 0; kk < 32; kk += 16) {
            wmma::fragment<wmma::matrix_a, 16, 16, 16, __nv_bfloat16, wmma::row_major> af[4];
            wmma::fragment<wmma::matrix_b, 16, 16, 16, __nv_bfloat16, wmma::col_major> bfr[4];
            #pragma unroll
            for (int i = 0; i < 4; i++)
                wmma::load_matrix_sync(af[i], &sA[cur][wm * 64 + i * 16][kk], SMLD);
            #pragma unroll
            for (int j = 0; j < 4; j++)
                wmma::load_matrix_sync(bfr[j], &sB[cur][wn * 64 + j * 16][kk], SMLD);
            #pragma unroll
            for (int i = 0; i < 4; i++)
                #pragma unroll
                for (int j = 0; j < 4; j++)
                    wmma::mma_sync(cf[i][j], af[i], bfr[j], cf[i][j]);
        }
        if (t < 5) CP_WAIT0();
        __syncthreads();
    }

    // augmented tail k16: A=[1,1,0..], B=[hx_m,lx_m,0..]  -> adds -0.5*xx_m
    {
        const __nv_bfloat16 one = __float2bfloat16(1.0f);
        const __nv_bfloat16 zero = __float2bfloat16(0.0f);
        if (tid < 128) {
            sA[0][tid][0] = one; sA[0][tid][1] = one;
            #pragma unroll
            for (int c = 2; c < 16; c++) sA[0][tid][c] = zero;
        }
        sB[0][tid][0] = g_hx[bb + m0 + tid];
        sB[0][tid][1] = g_lx[bb + m0 + tid];
        #pragma unroll
        for (int c = 2; c < 16; c++) sB[0][tid][c] = zero;
        __syncthreads();
        wmma::fragment<wmma::matrix_a, 16, 16, 16, __nv_bfloat16, wmma::row_major> af[4];
        wmma::fragment<wmma::matrix_b, 16, 16, 16, __nv_bfloat16, wmma::col_major> bfr[4];
        #pragma unroll
        for (int i = 0; i < 4; i++)
            wmma::load_matrix_sync(af[i], &sA[0][wm * 64 + i * 16][0], SMLD);
        #pragma unroll
        for (int j = 0; j < 4; j++)
            wmma::load_matrix_sync(bfr[j], &sB[0][wn * 64 + j * 16][0], SMLD);
        #pragma unroll
        for (int i = 0; i < 4; i++)
            #pragma unroll
            for (int j = 0; j < 4; j++)
                wmma::mma_sync(cf[i][j], af[i], bfr[j], cf[i][j]);
    }

    // store raw scores
    #pragma unroll
    for (int i = 0; i < 4; i++)
        #pragma unroll
        for (int j = 0; j < 4; j++) {
            float* op = g_pdist + ((size_t)(bb + n0 + wm * 64 + i * 16)) * NPT
                        + m0 + wn * 64 + j * 16;
            wmma::store_matrix_sync(op, cf[i][j], NPT, wmma::mem_row_major);
        }

    // per-row 32-col-group maxes (reads back own stores; block-visible after sync)
    __syncthreads();
    {
        int row  = tid >> 1;
        int half = tid & 1;
        const float4* p = (const float4*)(g_pdist + (size_t)(bb + n0 + row) * NPT + m0 + half * 128);
        #pragma unroll
        for (int g = 0; g < 4; g++) {
            float mx = -INFINITY;
            #pragma unroll
            for (int j = 0; j < 8; j++) {
                float4 v = p[g * 8 + j];
                mx = fmaxf(mx, fmaxf(fmaxf(v.x, v.y), fmaxf(v.z, v.w)));
            }
            g_rtm[(size_t)(bb + n0 + row) * NGRP + blockIdx.x * 8 + half * 4 + g] = mx;
        }
    }
}

// ---------------- 3: group-skip threshold-collect top-TCAND per row (warp per row) ----------------
__global__ __launch_bounds__(256) void cand_kernel() {
    int gwarp = (blockIdx.x * blockDim.x + threadIdx.x) >> 5;   // row id [0,16384)
    int lane  = threadIdx.x & 31;
    int wl    = threadIdx.x >> 5;

    __shared__ float s_v[8][CCAP];
    __shared__ int   s_i[8][CCAP];
    __shared__ int   s_g[8][NGRP];

    // load 64 group maxima (2 per lane)
    const float* rtm = g_rtm + (size_t)gwarp * NGRP;
    float gm0 = rtm[lane];
    float gm1 = rtm[lane + 32];

    // tau = 16th-largest of the 64 group maxima (guarantees >=16 elements >= tau,
    // and approx-top-16 of the row is contained in {v >= tau})
    float a0 = gm0, a1 = gm1, tau = 0.f;
    #pragma unroll
    for (int r = 0; r < 16; r++) {
        float mx = fmaxf(a0, a1);
        #pragma unroll
        for (int off = 16; off; off >>= 1) mx = fmaxf(mx, __shfl_xor_sync(0xffffffff, mx, off));
        tau = mx;
        unsigned msk = __ballot_sync(0xffffffff, a0 == mx || a1 == mx);
        int src = __ffs(msk) - 1;
        if (lane == src) { if (a0 == mx) a0 = -INFINITY; else a1 = -INFINITY; }
    }

    // compact list of selected groups (max >= tau)
    unsigned m0s = __ballot_sync(0xffffffff, gm0 >= tau);
    unsigned m1s = __ballot_sync(0xffffffff, gm1 >= tau);
    unsigned lt = (1u << lane) - 1;
    int n0s = __popc(m0s);
    if (gm0 >= tau) s_g[wl][__popc(m0s & lt)] = lane;
    if (gm1 >= tau) s_g[wl][n0s + __popc(m1s & lt)] = 32 + lane;
    int nsel = n0s + __popc(m1s);
    __syncwarp();

    // scan only selected groups: 4 groups per iteration (8 lanes per group, 1 float4 each)
    const float4* row4 = (const float4*)(g_pdist + (size_t)gwarp * NPT);
    int base = 0;
    for (int c = 0; c < nsel; c += 4) {
        int gi  = c + (lane >> 3);
        int sub = lane & 7;
        bool act = gi < nsel;
        int grp = act ? s_g[wl][gi] : 0;
        int q = grp * 8 + sub;
        float4 v = act ? row4[q] : make_float4(-INFINITY, -INFINITY, -INFINITY, -INFINITY);
        float vals[4] = {v.x, v.y, v.z, v.w};
        float mx = fmaxf(fmaxf(vals[0], vals[1]), fmaxf(vals[2], vals[3]));
        unsigned any = __ballot_sync(0xffffffff, mx >= tau);
        if (any) {
            #pragma unroll
            for (int e = 0; e < 4; e++) {
                bool hit = vals[e] >= tau;
                unsigned m = __ballot_sync(0xffffffff, hit);
                if (m) {
                    if (hit) {
                        int pos = base + __popc(m & lt);
                        if (pos < CCAP) { s_v[wl][pos] = vals[e]; s_i[wl][pos] = q * 4 + e; }
                    }
                    base += __popc(m);
                }
            }
        }
    }
    int cnt = min(base, CCAP);
    __syncwarp();

    // top-TCAND of collected (value desc, index asc)
    int* out = g_cand + (size_t)gwarp * TCAND;
    for (int r = 0; r < TCAND; r++) {
        float bv = -INFINITY; int bi = 0x7fffffff;
        for (int t = lane; t < cnt; t += 32) {
            float vv = s_v[wl][t]; int ii = s_i[wl][t];
            if (vv > bv || (vv == bv && ii < bi)) { bv = vv; bi = ii; }
        }
        #pragma unroll
        for (int off = 16; off; off >>= 1) {
            float ov = __shfl_down_sync(0xffffffff, bv, off);
            int   oi = __shfl_down_sync(0xffffffff, bi, off);
            if (ov > bv || (ov == bv && oi < bi)) { bv = ov; bi = oi; }
        }
        bv = __shfl_sync(0xffffffff, bv, 0);
        bi = __shfl_sync(0xffffffff, bi, 0);
        if (lane == 0) out[r] = bi;
        for (int t = lane; t < cnt; t += 32)
            if (s_i[wl][t] == bi) s_v[wl][t] = -INFINITY;
        __syncwarp();
    }
}

// ---------------- 4: compensated-fp32 (Dot2) refine -> final top-KNN (+ fused counts) ----------------
__global__ __launch_bounds__(256) void refine_kernel() {
    int row  = (blockIdx.x * blockDim.x + threadIdx.x) >> 5;  // [0,16384)
    int lane = threadIdx.x & 31;
    int wl   = threadIdx.x >> 5;
    int b    = row >> 11;

    __shared__ float s_val[8][TCAND];
    __shared__ int   s_id[8][TCAND];

    float xn[6];
    #pragma unroll
    for (int u = 0; u < 6; u++) xn[u] = g_xt[(size_t)row * DTOT + lane + 32 * u];
    float xxn = (float)g_xx64[row];

    for (int j = 0; j < TCAND; j++) {
        int m = g_cand[(size_t)row * TCAND + j];
        const float* xm = g_xt + ((size_t)(b << 11) + m) * DTOT;
        float s = 0.0f, comp = 0.0f;
        #pragma unroll
        for (int u = 0; u < 6; u++) {
            float a = xn[u], bv = xm[lane + 32 * u];
            float p  = __fmul_rn(a, bv);
            float pe = __fmaf_rn(a, bv, -p);              // exact product error
            float t  = __fadd_rn(s, p);                   // Knuth TwoSum
            float z  = __fsub_rn(t, s);
            float e  = __fadd_rn(__fsub_rn(s, __fsub_rn(t, z)), __fsub_rn(p, z));
            s = t;
            comp = __fadd_rn(comp, __fadd_rn(e, pe));
        }
        #pragma unroll
        for (int off = 16; off; off >>= 1) {
            float os = __shfl_down_sync(0xffffffff, s,    off);
            float oc = __shfl_down_sync(0xffffffff, comp, off);
            float t  = __fadd_rn(s, os);
            float z  = __fsub_rn(t, s);
            float e  = __fadd_rn(__fsub_rn(s, __fsub_rn(t, z)), __fsub_rn(os, z));
            s = t;
            comp = __fadd_rn(comp, __fadd_rn(e, oc));
        }
        if (lane == 0) {
            // emulate reference's fp32 expression structure for tie alignment:
            float innerf = __fadd_rn(s, comp);
            float pf = 2.0f * innerf;
            pf = pf - xxn;
            pf = pf - (float)g_xx64[(size_t)(b << 11) + m];
            s_val[wl][j] = pf;
            s_id[wl][j]  = m;
        }
    }
    __syncwarp();

    if (lane == 0) {
        int* out = g_idx + (size_t)row * KNN;
        int bb = (row >> 11) << 11;
        for (int r = 0; r < KNN; r++) {
            float bv = -INFINITY; int bi = 0x7fffffff; int bs = 0;
            #pragma unroll
            for (int t = 0; t < TCAND; t++) {
                float v = s_val[wl][t]; int id = s_id[wl][t];
                if (v > bv || (v == bv && id < bi)) { bv = v; bi = id; bs = t; }
            }
            out[r] = bi;
            atomicAdd(&g_cnt[bb + bi], 1);
            s_val[wl][bs] = -INFINITY;
        }
    }
}

// ---------------- 5: y_feat / y_dir  [bm][od] ----------------
__global__ void feat_kernel(const float* __restrict__ x,
                            const float* __restrict__ Wf,
                            const float* __restrict__ Wd) {
    __shared__ float wfs[64][64];   // [c][o]
    __shared__ float wds[64][64];
    __shared__ float xs[DTOT][16];

    int b = blockIdx.y;
    int n0 = blockIdx.x * 16;
    int tid = threadIdx.x;          // 192

    for (int i = tid; i < 4096; i += 192) {
        int o = i >> 6, c = i & 63;
        wfs[c][o] = Wf[i];
        wds[c][o] = Wd[i];
    }
    const float* X = x + (size_t)b * DTOT * NPT;
    for (int i = tid; i < DTOT * 16; i += 192) {
        int c3 = i >> 4, n = i & 15;
        xs[c3][n] = X[(size_t)c3 * NPT + n0 + n];
    }
    __syncthreads();

    int o = tid / 3;
    int d = tid - 3 * o;

    float af[16], ad_[16];
    #pragma unroll
    for (int n = 0; n < 16; n++) { af[n] = 0.f; ad_[n] = 0.f; }

    for (int c = 0; c < 64; c++) {
        float wf = wfs[c][o], wd = wds[c][o];
        #pragma unroll
        for (int n = 0; n < 16; n++) {
            float xv = xs[c * 3 + d][n];
            af[n]  = fmaf(wf, xv, af[n]);
            ad_[n] = fmaf(wd, xv, ad_[n]);
        }
    }
    #pragma unroll
    for (int n = 0; n < 16; n++) {
        size_t base = ((size_t)b * NPT + n0 + n) * DTOT + tid;
        g_yf[base] = af[n];
        g_yd[base] = ad_[n];
    }
}

// ---------------- 6: per-point norm / f·d / |d|^2 ----------------
__global__ void pstat_kernel() {
    int t = blockIdx.x * blockDim.x + threadIdx.x;  // 16384*64
    int bm = t >> 6;
    int o  = t & 63;
    const float* f = g_yf + (size_t)bm * DTOT + o * 3;
    const float* g = g_yd + (size_t)bm * DTOT + o * 3;
    float f0 = f[0], f1 = f[1], f2 = f[2];
    float g0 = g[0], g1 = g[1], g2 = g[2];
    g_nrm[t] = sqrtf(f0 * f0 + f1 * f1 + f2 * f2);
    g_dfd[t] = f0 * g0 + f1 * g1 + f2 * g2;
    g_dsq[t] = g0 * g0 + g1 * g1 + g2 * g2;
}

// ---------------- 8: BN stats (count-weighted, exact) ----------------
__global__ void bnstat_kernel(const float* __restrict__ gamma, const float* __restrict__ beta) {
    int o = blockIdx.x;
    int tid = threadIdx.x;  // 256
    double s1 = 0.0, s2 = 0.0;
    for (int bm = tid; bm < NPAIR; bm += 256) {
        float v = g_nrm[(size_t)bm * COUT + o];
        double c = (double)g_cnt[bm];
        s1 += c * v;
        s2 += c * (double)v * (double)v;
    }
    __shared__ double r1[256], r2[256];
    r1[tid] = s1; r2[tid] = s2;
    __syncthreads();
    for (int s = 128; s; s >>= 1) {
        if (tid < s) { r1[tid] += r1[tid + s]; r2[tid] += r2[tid + s]; }
        __syncthreads();
    }
    if (tid == 0) {
        const double cnt = (double)NEDGE;
        double mean = r1[0] / cnt;
        double var  = r2[0] / cnt - mean * mean;
        double a = (double)gamma[o] / sqrt(var + (double)BN_EPS);
        g_chA[o] = (float)a;
        g_chB[o] = (float)((double)beta[o] - mean * a);
    }
}

// ---------------- 9: per-point output vectors v ----------------
__global__ void v_kernel() {
    int bm = blockIdx.x;
    int od = threadIdx.x;       // 192
    int o = od / 3;
    size_t t = (size_t)bm * DTOT + od;
    size_t s = (size_t)bm * COUT + o;
    float n    = g_nrm[s];
    float scale = g_chA[o] + g_chB[o] / n;     // norm_bn / norm
    float dot  = scale * g_dfd[s];
    float pv   = scale * g_yf[t];
    float outv = pv;
    if (dot < 0.f) outv = pv - dot / (g_dsq[s] + VN_EPS) * g_yd[t];
    g_v[t] = outv;
}

// ---------------- 10: gather-mean to output ----------------
__global__ void gather_kernel(float* __restrict__ out) {
    __shared__ int sidx[16 * KNN];
    int b  = blockIdx.y;
    int n0 = blockIdx.x * 16;
    int tid = threadIdx.x;      // 192
    if (tid < 16 * KNN) sidx[tid] = g_idx[((size_t)b * NPT + n0) * KNN + tid];
    __syncthreads();

    const float* vb = g_v + (size_t)b * NPT * DTOT;
    float res[16];
    #pragma unroll
    for (int n = 0; n < 16; n++) {
        float acc = 0.f;
        #pragma unroll
        for (int k = 0; k < KNN; k++) {
            int m = sidx[n * KNN + k];
            acc += vb[(size_t)m * DTOT + tid];
        }
        res[n] = acc * (1.0f / (float)KNN);
    }
    float* ob = out + ((size_t)b * DTOT + tid) * NPT + n0;
    *(float4*)(ob)      = make_float4(res[0],  res[1],  res[2],  res[3]);
    *(float4*)(ob + 4)  = make_float4(res[4],  res[5],  res[6],  res[7]);
    *(float4*)(ob + 8)  = make_float4(res[8],  res[9],  res[10], res[11]);
    *(float4*)(ob + 12) = make_float4(res[12], res[13], res[14], res[15]);
}

// ---------------- launch ----------------
extern "C" void kernel_launch(void* const* d_in, const int* in_sizes, int n_in,
                              void* d_out, int out_size) {
    const float* x     = (const float*)d_in[0];
    const float* Wf    = (const float*)d_in[1];
    const float* Wd    = (const float*)d_in[2];
    const float* gamma = (const float*)d_in[3];
    const float* beta  = (const float*)d_in[4];
    float* out = (float*)d_out;

    cudaFuncSetAttribute(knn_wmma, cudaFuncAttributeMaxDynamicSharedMemorySize, KNN_SMEM);

    xt_kernel<<<dim3(NPT / 32, DTOT / 32, BATCH), dim3(32, 32)>>>(x);
    xx64_kernel<<<NPAIR / 256, 256>>>();
    knn_wmma<<<dim3(NPT / 256, NPT / 128, BATCH), 256, KNN_SMEM>>>();
    cand_kernel<<<NPAIR / 8, 256>>>();
    refine_kernel<<<NPAIR / 8, 256>>>();
    feat_kernel<<<dim3(NPT / 16, BATCH), 192>>>(x, Wf, Wd);
    pstat_kernel<<<(NPAIR * COUT) / 256, 256>>>();
    bnstat_kernel<<<COUT, 256>>>(gamma, beta);
    v_kernel<<<NPAIR, DTOT>>>();
    gather_kernel<<<dim3(NPT / 16, BATCH), DTOT>>>(out);
}

// round 16
// speedup vs baseline: 1.3351x; 1.0023x over previous
#include <cuda_runtime.h>
#include <cuda_bf16.h>
#include <mma.h>
#include <math.h>
#include <stdint.h>

using namespace nvcuda;

// Problem constants (fixed by the bench)
#define BATCH 8
#define CIN   64
#define COUT  64
#define NPT   2048
#define DTOT  192           // 3*Cin feature dim for kNN
#define KNN   11            // k+1
#define NPAIR (BATCH*NPT)   // 16384 points total
#define NEDGE (BATCH*NPT*KNN)
#define TCAND 16            // candidates kept per row before exact refine
#define CCAP  320           // per-row candidate collection capacity
#define NGRP  64            // 32-col groups per row

#define VN_EPS 1e-6f
#define BN_EPS 1e-5f

// ---------------- scratch (device globals; no cudaMalloc allowed) ----------------
__device__ float          g_pdist[(size_t)BATCH * NPT * NPT];   // 134 MB (rank scores)
__device__ float          g_rtm[(size_t)NPAIR * NGRP];          // per-row per-32col-group max
__device__ float          g_xt[(size_t)NPAIR * DTOT];           // transposed x: [bm][d]
__device__ __nv_bfloat16  g_hi[(size_t)NPAIR * DTOT];           // bf16 of xt
__device__ double         g_xx64[NPAIR];
__device__ __nv_bfloat16  g_hx[NPAIR];                          // bf16 hi of -0.5*xx
__device__ __nv_bfloat16  g_lx[NPAIR];                          // bf16 lo of -0.5*xx
__device__ int            g_cand[(size_t)NPAIR * TCAND];
__device__ int            g_idx[NEDGE];
__device__ float          g_yf[(size_t)NPAIR * DTOT];           // [bm][o*3+d]
__device__ float          g_yd[(size_t)NPAIR * DTOT];
__device__ float          g_nrm[(size_t)NPAIR * COUT];          // [bm][o]
__device__ float          g_dfd[(size_t)NPAIR * COUT];
__device__ float          g_dsq[(size_t)NPAIR * COUT];
__device__ float          g_v[(size_t)NPAIR * DTOT];            // per-point output vectors
__device__ int            g_cnt[NPAIR];
__device__ double         g_bnpart[64][COUT][2];                // phase-1 BN partials
__device__ float          g_chA[COUT];
__device__ float          g_chB[COUT];

// ---------------- cp.async helpers ----------------
__device__ __forceinline__ void cp16(void* s, const void* g) {
    unsigned int sa = (unsigned int)__cvta_generic_to_shared(s);
    asm volatile("cp.async.cg.shared.global [%0], [%1], 16;" :: "r"(sa), "l"(g));
}
#define CP_COMMIT() asm volatile("cp.async.commit_group;" ::: "memory")
#define CP_WAIT0()  asm volatile("cp.async.wait_group 0;" ::: "memory")

// ---------------- 0: transpose x -> g_xt [bm][d]; emit bf16 ----------------
__global__ void xt_kernel(const float* __restrict__ x) {
    __shared__ float t[32][33];
    int b  = blockIdx.z;
    int d0 = blockIdx.y * 32;
    int n0 = blockIdx.x * 32;
    const float* X = x + (size_t)b * DTOT * NPT;
    t[threadIdx.y][threadIdx.x] = X[(size_t)(d0 + threadIdx.y) * NPT + n0 + threadIdx.x];
    __syncthreads();
    float v = t[threadIdx.x][threadIdx.y];
    size_t o = ((size_t)(b << 11) + n0 + threadIdx.y) * DTOT + d0 + threadIdx.x;
    g_xt[o] = v;
    g_hi[o] = __float2bfloat16(v);
}

// ---------------- 1: xx in fp64 (exact) + bf16 hi/lo of -0.5*xx; zero counts ----------------
__global__ void xx64_kernel() {
    int p = blockIdx.x * blockDim.x + threadIdx.x;      // 16384 points
    const float* r = g_xt + (size_t)p * DTOT;
    double s = 0.0;
    #pragma unroll 8
    for (int d = 0; d < DTOT; d++) { double v = (double)r[d]; s += v * v; }
    g_xx64[p] = s;
    float m05 = (float)(-0.5 * s);
    __nv_bfloat16 hx = __float2bfloat16(m05);
    g_hx[p] = hx;
    g_lx[p] = __float2bfloat16(m05 - __bfloat162float(hx));
    g_cnt[p] = 0;
}

// ---------------- 2: tensor-core rank-score GEMM (128x256 tile, cp.async pipeline) ----------------
// score[n][m] = x_n.x_m - 0.5*xx_m   (per-row-monotone transform of pdist)
#define SMLD 40   // smem row stride (bf16 elems), pad 8 to kill conflicts
#define KNN_SMEM (2*128*SMLD*2 + 2*256*SMLD*2)   // 61440 B

__global__ __launch_bounds__(256) void knn_wmma() {
    extern __shared__ char dsm[];
    __nv_bfloat16 (*sA)[128][SMLD] = reinterpret_cast<__nv_bfloat16 (*)[128][SMLD]>(dsm);
    __nv_bfloat16 (*sB)[256][SMLD] = reinterpret_cast<__nv_bfloat16 (*)[256][SMLD]>(dsm + 2 * 128 * SMLD * 2);

    int bb = blockIdx.z << 11;
    int n0 = blockIdx.y * 128;
    int m0 = blockIdx.x * 256;

    int tid  = threadIdx.x;
    int warp = tid >> 5;
    int wm   = warp & 1;    // 2 warps along rows (n), 64 each
    int wn   = warp >> 1;   // 4 warps along cols (m), 64 each

    auto load_chunk = [&](int buf, int dof) {
        #pragma unroll
        for (int r = 0; r < 2; r++) {
            int s = tid + r * 256;          // 512 A slots
            int row = s >> 2, c8 = (s & 3) * 8;
            cp16(&sA[buf][row][c8], &g_hi[(size_t)(bb + n0 + row) * DTOT + dof + c8]);
        }
        #pragma unroll
        for (int r = 0; r < 4; r++) {
            int s = tid + r * 256;          // 1024 B slots
            int row = s >> 2, c8 = (s & 3) * 8;
            cp16(&sB[buf][row][c8], &g_hi[(size_t)(bb + m0 + row) * DTOT + dof + c8]);
        }
    };

    wmma::fragment<wmma::accumulator, 16, 16, 16, float> cf[4][4];
    #pragma unroll
    for (int i = 0; i < 4; i++)
        #pragma unroll
        for (int j = 0; j < 4; j++) wmma::fill_fragment(cf[i][j], 0.0f);

    // prologue
    load_chunk(0, 0);
    CP_COMMIT();
    CP_WAIT0();
    __syncthreads();

    // 6 chunks of BK=32 over K=192: [issue next via cp.async | compute cur | wait | sync]
    for (int t = 0; t < 6; t++) {
        if (t < 5) { load_chunk((t + 1) & 1, (t + 1) * 32); CP_COMMIT(); }
        int cur = t & 1;
        #pragma unroll
        for (int kk = 0; kk < 32; kk += 16) {
            wmma::fragment<wmma::matrix_a, 16, 16, 16, __nv_bfloat16, wmma::row_major> af[4];
            wmma::fragment<wmma::matrix_b, 16, 16, 16, __nv_bfloat16, wmma::col_major> bfr[4];
            #pragma unroll
            for (int i = 0; i < 4; i++)
                wmma::load_matrix_sync(af[i], &sA[cur][wm * 64 + i * 16][kk], SMLD);
            #pragma unroll
            for (int j = 0; j < 4; j++)
                wmma::load_matrix_sync(bfr[j], &sB[cur][wn * 64 + j * 16][kk], SMLD);
            #pragma unroll
            for (int i = 0; i < 4; i++)
                #pragma unroll
                for (int j = 0; j < 4; j++)
                    wmma::mma_sync(cf[i][j], af[i], bfr[j], cf[i][j]);
        }
        if (t < 5) CP_WAIT0();
        __syncthreads();
    }

    // augmented tail k16: A=[1,1,0..], B=[hx_m,lx_m,0..]  -> adds -0.5*xx_m
    {
        const __nv_bfloat16 one = __float2bfloat16(1.0f);
        const __nv_bfloat16 zero = __float2bfloat16(0.0f);
        if (tid < 128) {
            sA[0][tid][0] = one; sA[0][tid][1] = one;
            #pragma unroll
            for (int c = 2; c < 16; c++) sA[0][tid][c] = zero;
        }
        sB[0][tid][0] = g_hx[bb + m0 + tid];
        sB[0][tid][1] = g_lx[bb + m0 + tid];
        #pragma unroll
        for (int c = 2; c < 16; c++) sB[0][tid][c] = zero;
        __syncthreads();
        wmma::fragment<wmma::matrix_a, 16, 16, 16, __nv_bfloat16, wmma::row_major> af[4];
        wmma::fragment<wmma::matrix_b, 16, 16, 16, __nv_bfloat16, wmma::col_major> bfr[4];
        #pragma unroll
        for (int i = 0; i < 4; i++)
            wmma::load_matrix_sync(af[i], &sA[0][wm * 64 + i * 16][0], SMLD);
        #pragma unroll
        for (int j = 0; j < 4; j++)
            wmma::load_matrix_sync(bfr[j], &sB[0][wn * 64 + j * 16][0], SMLD);
        #pragma unroll
        for (int i = 0; i < 4; i++)
            #pragma unroll
            for (int j = 0; j < 4; j++)
                wmma::mma_sync(cf[i][j], af[i], bfr[j], cf[i][j]);
    }

    // store raw scores
    #pragma unroll
    for (int i = 0; i < 4; i++)
        #pragma unroll
        for (int j = 0; j < 4; j++) {
            float* op = g_pdist + ((size_t)(bb + n0 + wm * 64 + i * 16)) * NPT
                        + m0 + wn * 64 + j * 16;
            wmma::store_matrix_sync(op, cf[i][j], NPT, wmma::mem_row_major);
        }

    // per-row 32-col-group maxes (reads back own stores; block-visible after sync)
    __syncthreads();
    {
        int row  = tid >> 1;
        int half = tid & 1;
        const float4* p = (const float4*)(g_pdist + (size_t)(bb + n0 + row) * NPT + m0 + half * 128);
        #pragma unroll
        for (int g = 0; g < 4; g++) {
            float mx = -INFINITY;
            #pragma unroll
            for (int j = 0; j < 8; j++) {
                float4 v = p[g * 8 + j];
                mx = fmaxf(mx, fmaxf(fmaxf(v.x, v.y), fmaxf(v.z, v.w)));
            }
            g_rtm[(size_t)(bb + n0 + row) * NGRP + blockIdx.x * 8 + half * 4 + g] = mx;
        }
    }
}

// ---------------- 3: group-skip threshold-collect top-TCAND per row (warp per row) ----------------
__global__ __launch_bounds__(256) void cand_kernel() {
    int gwarp = (blockIdx.x * blockDim.x + threadIdx.x) >> 5;   // row id [0,16384)
    int lane  = threadIdx.x & 31;
    int wl    = threadIdx.x >> 5;

    __shared__ float s_v[8][CCAP];
    __shared__ int   s_i[8][CCAP];
    __shared__ int   s_g[8][NGRP];

    // load 64 group maxima (2 per lane)
    const float* rtm = g_rtm + (size_t)gwarp * NGRP;
    float gm0 = rtm[lane];
    float gm1 = rtm[lane + 32];

    // tau = 16th-largest of the 64 group maxima (guarantees >=16 elements >= tau,
    // and approx-top-16 of the row is contained in {v >= tau})
    float a0 = gm0, a1 = gm1, tau = 0.f;
    #pragma unroll
    for (int r = 0; r < 16; r++) {
        float mx = fmaxf(a0, a1);
        #pragma unroll
        for (int off = 16; off; off >>= 1) mx = fmaxf(mx, __shfl_xor_sync(0xffffffff, mx, off));
        tau = mx;
        unsigned msk = __ballot_sync(0xffffffff, a0 == mx || a1 == mx);
        int src = __ffs(msk) - 1;
        if (lane == src) { if (a0 == mx) a0 = -INFINITY; else a1 = -INFINITY; }
    }

    // compact list of selected groups (max >= tau)
    unsigned m0s = __ballot_sync(0xffffffff, gm0 >= tau);
    unsigned m1s = __ballot_sync(0xffffffff, gm1 >= tau);
    unsigned lt = (1u << lane) - 1;
    int n0s = __popc(m0s);
    if (gm0 >= tau) s_g[wl][__popc(m0s & lt)] = lane;
    if (gm1 >= tau) s_g[wl][n0s + __popc(m1s & lt)] = 32 + lane;
    int nsel = n0s + __popc(m1s);
    __syncwarp();

    // scan only selected groups: 4 groups per iteration (8 lanes per group, 1 float4 each)
    const float4* row4 = (const float4*)(g_pdist + (size_t)gwarp * NPT);
    int base = 0;
    for (int c = 0; c < nsel; c += 4) {
        int gi  = c + (lane >> 3);
        int sub = lane & 7;
        bool act = gi < nsel;
        int grp = act ? s_g[wl][gi] : 0;
        int q = grp * 8 + sub;
        float4 v = act ? row4[q] : make_float4(-INFINITY, -INFINITY, -INFINITY, -INFINITY);
        float vals[4] = {v.x, v.y, v.z, v.w};
        float mx = fmaxf(fmaxf(vals[0], vals[1]), fmaxf(vals[2], vals[3]));
        unsigned any = __ballot_sync(0xffffffff, mx >= tau);
        if (any) {
            #pragma unroll
            for (int e = 0; e < 4; e++) {
                bool hit = vals[e] >= tau;
                unsigned m = __ballot_sync(0xffffffff, hit);
                if (m) {
                    if (hit) {
                        int pos = base + __popc(m & lt);
                        if (pos < CCAP) { s_v[wl][pos] = vals[e]; s_i[wl][pos] = q * 4 + e; }
                    }
                    base += __popc(m);
                }
            }
        }
    }
    int cnt = min(base, CCAP);
    __syncwarp();

    int* out = g_cand + (size_t)gwarp * TCAND;
    if (cnt <= 128) {
        // fast path: load collected set into 4 regs/lane, extract top-16 in registers
        float rv[4]; int ri[4];
        #pragma unroll
        for (int j = 0; j < 4; j++) {
            int idx = lane + 32 * j;
            bool a = idx < cnt;
            rv[j] = a ? s_v[wl][idx] : -INFINITY;
            ri[j] = a ? s_i[wl][idx] : 0x7fffffff;
        }
        for (int r = 0; r < TCAND; r++) {
            float bv = -INFINITY; int bi = 0x7fffffff;
            #pragma unroll
            for (int j = 0; j < 4; j++)
                if (rv[j] > bv || (rv[j] == bv && ri[j] < bi)) { bv = rv[j]; bi = ri[j]; }
            #pragma unroll
            for (int off = 16; off; off >>= 1) {
                float ov = __shfl_down_sync(0xffffffff, bv, off);
                int   oi = __shfl_down_sync(0xffffffff, bi, off);
                if (ov > bv || (ov == bv && oi < bi)) { bv = ov; bi = oi; }
            }
            bi = __shfl_sync(0xffffffff, bi, 0);
            if (lane == 0) out[r] = bi;
            #pragma unroll
            for (int j = 0; j < 4; j++)
                if (ri[j] == bi) rv[j] = -INFINITY;
        }
    } else {
        // fallback: smem scan extraction (rare)
        for (int r = 0; r < TCAND; r++) {
            float bv = -INFINITY; int bi = 0x7fffffff;
            for (int t = lane; t < cnt; t += 32) {
                float vv = s_v[wl][t]; int ii = s_i[wl][t];
                if (vv > bv || (vv == bv && ii < bi)) { bv = vv; bi = ii; }
            }
            #pragma unroll
            for (int off = 16; off; off >>= 1) {
                float ov = __shfl_down_sync(0xffffffff, bv, off);
                int   oi = __shfl_down_sync(0xffffffff, bi, off);
                if (ov > bv || (ov == bv && oi < bi)) { bv = ov; bi = oi; }
            }
            bv = __shfl_sync(0xffffffff, bv, 0);
            bi = __shfl_sync(0xffffffff, bi, 0);
            if (lane == 0) out[r] = bi;
            for (int t = lane; t < cnt; t += 32)
                if (s_i[wl][t] == bi) s_v[wl][t] = -INFINITY;
            __syncwarp();
        }
    }
}

// ---------------- 4: compensated-fp32 (Dot2) refine -> final top-KNN (+ fused counts) ----------------
__global__ __launch_bounds__(256) void refine_kernel() {
    int row  = (blockIdx.x * blockDim.x + threadIdx.x) >> 5;  // [0,16384)
    int lane = threadIdx.x & 31;
    int wl   = threadIdx.x >> 5;
    int b    = row >> 11;

    __shared__ float s_val[8][TCAND];
    __shared__ int   s_id[8][TCAND];

    float xn[6];
    #pragma unroll
    for (int u = 0; u < 6; u++) xn[u] = g_xt[(size_t)row * DTOT + lane + 32 * u];
    float xxn = (float)g_xx64[row];

    for (int j = 0; j < TCAND; j++) {
        int m = g_cand[(size_t)row * TCAND + j];
        const float* xm = g_xt + ((size_t)(b << 11) + m) * DTOT;
        float s = 0.0f, comp = 0.0f;
        #pragma unroll
        for (int u = 0; u < 6; u++) {
            float a = xn[u], bv = xm[lane + 32 * u];
            float p  = __fmul_rn(a, bv);
            float pe = __fmaf_rn(a, bv, -p);              // exact product error
            float t  = __fadd_rn(s, p);                   // Knuth TwoSum
            float z  = __fsub_rn(t, s);
            float e  = __fadd_rn(__fsub_rn(s, __fsub_rn(t, z)), __fsub_rn(p, z));
            s = t;
            comp = __fadd_rn(comp, __fadd_rn(e, pe));
        }
        #pragma unroll
        for (int off = 16; off; off >>= 1) {
            float os = __shfl_down_sync(0xffffffff, s,    off);
            float oc = __shfl_down_sync(0xffffffff, comp, off);
            float t  = __fadd_rn(s, os);
            float z  = __fsub_rn(t, s);
            float e  = __fadd_rn(__fsub_rn(s, __fsub_rn(t, z)), __fsub_rn(os, z));
            s = t;
            comp = __fadd_rn(comp, __fadd_rn(e, oc));
        }
        if (lane == 0) {
            // emulate reference's fp32 expression structure for tie alignment:
            float innerf = __fadd_rn(s, comp);
            float pf = 2.0f * innerf;
            pf = pf - xxn;
            pf = pf - (float)g_xx64[(size_t)(b << 11) + m];
            s_val[wl][j] = pf;
            s_id[wl][j]  = m;
        }
    }
    __syncwarp();

    if (lane == 0) {
        int* out = g_idx + (size_t)row * KNN;
        int bb = (row >> 11) << 11;
        for (int r = 0; r < KNN; r++) {
            float bv = -INFINITY; int bi = 0x7fffffff; int bs = 0;
            #pragma unroll
            for (int t = 0; t < TCAND; t++) {
                float v = s_val[wl][t]; int id = s_id[wl][t];
                if (v > bv || (v == bv && id < bi)) { bv = v; bi = id; bs = t; }
            }
            out[r] = bi;
            atomicAdd(&g_cnt[bb + bi], 1);
            s_val[wl][bs] = -INFINITY;
        }
    }
}

// ---------------- 5: y_feat / y_dir [bm][od]  + fused per-point stats ----------------
__global__ void feat_kernel(const float* __restrict__ x,
                            const float* __restrict__ Wf,
                            const float* __restrict__ Wd) {
    __shared__ float wfs[64][64];   // [c][o]; reused as sf stage after compute
    __shared__ float wds[64][64];   //          reused as sd stage
    __shared__ float xs[DTOT][16];

    int b = blockIdx.y;
    int n0 = blockIdx.x * 16;
    int tid = threadIdx.x;          // 192

    for (int i = tid; i < 4096; i += 192) {
        int o = i >> 6, c = i & 63;
        wfs[c][o] = Wf[i];
        wds[c][o] = Wd[i];
    }
    const float* X = x + (size_t)b * DTOT * NPT;
    for (int i = tid; i < DTOT * 16; i += 192) {
        int c3 = i >> 4, n = i & 15;
        xs[c3][n] = X[(size_t)c3 * NPT + n0 + n];
    }
    __syncthreads();

    int o = tid / 3;
    int d = tid - 3 * o;

    float af[16], ad_[16];
    #pragma unroll
    for (int n = 0; n < 16; n++) { af[n] = 0.f; ad_[n] = 0.f; }

    for (int c = 0; c < 64; c++) {
        float wf = wfs[c][o], wd = wds[c][o];
        #pragma unroll
        for (int n = 0; n < 16; n++) {
            float xv = xs[c * 3 + d][n];
            af[n]  = fmaf(wf, xv, af[n]);
            ad_[n] = fmaf(wd, xv, ad_[n]);
        }
    }
    #pragma unroll
    for (int n = 0; n < 16; n++) {
        size_t base = ((size_t)b * NPT + n0 + n) * DTOT + tid;
        g_yf[base] = af[n];
        g_yd[base] = ad_[n];
    }

    // fused pstat: stage af/ad_ into reused smem (pad 17, conflict-free), compute stats
    __syncthreads();                    // done reading wfs/wds
    float* sf = &wfs[0][0];             // 192*17 = 3264 floats <= 4096
    float* sd = &wds[0][0];
    #pragma unroll
    for (int n = 0; n < 16; n++) {
        sf[tid * 17 + n] = af[n];
        sd[tid * 17 + n] = ad_[n];
    }
    __syncthreads();
    for (int i = tid; i < 1024; i += 192) {
        int n = i >> 6, oo = i & 63;    // o fast -> coalesced global writes
        float f0 = sf[(oo * 3 + 0) * 17 + n];
        float f1 = sf[(oo * 3 + 1) * 17 + n];
        float f2 = sf[(oo * 3 + 2) * 17 + n];
        float g0 = sd[(oo * 3 + 0) * 17 + n];
        float g1 = sd[(oo * 3 + 1) * 17 + n];
        float g2 = sd[(oo * 3 + 2) * 17 + n];
        size_t t = ((size_t)b * NPT + n0 + n) * COUT + oo;
        g_nrm[t] = sqrtf(f0 * f0 + f1 * f1 + f2 * f2);
        g_dfd[t] = f0 * g0 + f1 * g1 + f2 * g2;
        g_dsq[t] = g0 * g0 + g1 * g1 + g2 * g2;
    }
}

// ---------------- 8a: BN stats phase 1 — coalesced count-weighted partials ----------------
__global__ void bnpart_kernel() {
    int p = blockIdx.x;      // 64 blocks, each covers 256 bm
    int t = threadIdx.x;     // 256
    int g = t >> 6, o = t & 63;
    double s1 = 0.0, s2 = 0.0;
    for (int i = 0; i < 64; i++) {
        int bm = p * 256 + g + 4 * i;
        float v = g_nrm[(size_t)bm * COUT + o];   // threads read consecutive addrs
        double c = (double)g_cnt[bm];
        s1 += c * v;
        s2 += c * (double)v * (double)v;
    }
    __shared__ double r1[256], r2[256];
    r1[t] = s1; r2[t] = s2;
    __syncthreads();
    if (t < 64) {
        g_bnpart[p][t][0] = r1[t] + r1[t + 64] + r1[t + 128] + r1[t + 192];
        g_bnpart[p][t][1] = r2[t] + r2[t + 64] + r2[t + 128] + r2[t + 192];
    }
}

// ---------------- 8b: BN stats phase 2 — final reduce -> chA/chB ----------------
__global__ void bnfinal_kernel(const float* __restrict__ gamma, const float* __restrict__ beta) {
    int o = threadIdx.x;     // 64
    double s1 = 0.0, s2 = 0.0;
    for (int p = 0; p < 64; p++) {
        s1 += g_bnpart[p][o][0];
        s2 += g_bnpart[p][o][1];
    }
    const double cnt = (double)NEDGE;
    double mean = s1 / cnt;
    double var  = s2 / cnt - mean * mean;
    double a = (double)gamma[o] / sqrt(var + (double)BN_EPS);
    g_chA[o] = (float)a;
    g_chB[o] = (float)((double)beta[o] - mean * a);
}

// ---------------- 9: per-point output vectors v ----------------
__global__ void v_kernel() {
    int bm = blockIdx.x;
    int od = threadIdx.x;       // 192
    int o = od / 3;
    size_t t = (size_t)bm * DTOT + od;
    size_t s = (size_t)bm * COUT + o;
    float n    = g_nrm[s];
    float scale = g_chA[o] + g_chB[o] / n;     // norm_bn / norm
    float dot  = scale * g_dfd[s];
    float pv   = scale * g_yf[t];
    float outv = pv;
    if (dot < 0.f) outv = pv - dot / (g_dsq[s] + VN_EPS) * g_yd[t];
    g_v[t] = outv;
}

// ---------------- 10: gather-mean to output ----------------
__global__ void gather_kernel(float* __restrict__ out) {
    __shared__ int sidx[16 * KNN];
    int b  = blockIdx.y;
    int n0 = blockIdx.x * 16;
    int tid = threadIdx.x;      // 192
    if (tid < 16 * KNN) sidx[tid] = g_idx[((size_t)b * NPT + n0) * KNN + tid];
    __syncthreads();

    const float* vb = g_v + (size_t)b * NPT * DTOT;
    float res[16];
    #pragma unroll
    for (int n = 0; n < 16; n++) {
        float acc = 0.f;
        #pragma unroll
        for (int k = 0; k < KNN; k++) {
            int m = sidx[n * KNN + k];
            acc += vb[(size_t)m * DTOT + tid];
        }
        res[n] = acc * (1.0f / (float)KNN);
    }
    float* ob = out + ((size_t)b * DTOT + tid) * NPT + n0;
    *(float4*)(ob)      = make_float4(res[0],  res[1],  res[2],  res[3]);
    *(float4*)(ob + 4)  = make_float4(res[4],  res[5],  res[6],  res[7]);
    *(float4*)(ob + 8)  = make_float4(res[8],  res[9],  res[10], res[11]);
    *(float4*)(ob + 12) = make_float4(res[12], res[13], res[14], res[15]);
}

// ---------------- launch ----------------
extern "C" void kernel_launch(void* const* d_in, const int* in_sizes, int n_in,
                              void* d_out, int out_size) {
    const float* x     = (const float*)d_in[0];
    const float* Wf    = (const float*)d_in[1];
    const float* Wd    = (const float*)d_in[2];
    const float* gamma = (const float*)d_in[3];
    const float* beta  = (const float*)d_in[4];
    float* out = (float*)d_out;

    cudaFuncSetAttribute(knn_wmma, cudaFuncAttributeMaxDynamicSharedMemorySize, KNN_SMEM);

    xt_kernel<<<dim3(NPT / 32, DTOT / 32, BATCH), dim3(32, 32)>>>(x);
    xx64_kernel<<<NPAIR / 256, 256>>>();
    knn_wmma<<<dim3(NPT / 256, NPT / 128, BATCH), 256, KNN_SMEM>>>();
    cand_kernel<<<NPAIR / 8, 256>>>();
    refine_kernel<<<NPAIR / 8, 256>>>();
    feat_kernel<<<dim3(NPT / 16, BATCH), 192>>>(x, Wf, Wd);
    bnpart_kernel<<<64, 256>>>();
    bnfinal_kernel<<<1, 64>>>(gamma, beta);
    v_kernel<<<NPAIR, DTOT>>>();
    gather_kernel<<<dim3(NPT / 16, BATCH), DTOT>>>(out);
}

// round 17
// speedup vs baseline: 1.3928x; 1.0432x over previous
#include <cuda_runtime.h>
#include <cuda_bf16.h>
#include <mma.h>
#include <math.h>
#include <stdint.h>

using namespace nvcuda;

// Problem constants (fixed by the bench)
#define BATCH 8
#define CIN   64
#define COUT  64
#define NPT   2048
#define DTOT  192           // 3*Cin feature dim for kNN
#define KNN   11            // k+1
#define NPAIR (BATCH*NPT)   // 16384 points total
#define NEDGE (BATCH*NPT*KNN)
#define TCAND 16            // candidates kept per row before exact refine
#define CCAP  320           // per-row candidate collection capacity
#define NGRP  64            // 32-col groups per row
#define NTILE 16            // 128-wide tiles per batch row/col
#define NPAIRS_TRI (NTILE*(NTILE+1)/2)   // 136 upper-tri tiles

#define VN_EPS 1e-6f
#define BN_EPS 1e-5f

// ---------------- scratch (device globals; no cudaMalloc allowed) ----------------
__device__ float          g_pdist[(size_t)BATCH * NPT * NPT];   // 134 MB (rank scores)
__device__ float          g_rtm[(size_t)NPAIR * NGRP];          // per-row per-32col-group max
__device__ float          g_xt[(size_t)NPAIR * DTOT];           // transposed x: [bm][d]
__device__ __nv_bfloat16  g_hi[(size_t)NPAIR * DTOT];           // bf16 of xt
__device__ double         g_xx64[NPAIR];
__device__ float          g_mxx[NPAIR];                         // -0.5*xx (fp32)
__device__ int            g_cand[(size_t)NPAIR * TCAND];
__device__ int            g_idx[NEDGE];
__device__ float          g_yf[(size_t)NPAIR * DTOT];           // [bm][o*3+d]
__device__ float          g_yd[(size_t)NPAIR * DTOT];
__device__ float          g_nrm[(size_t)NPAIR * COUT];          // [bm][o]
__device__ float          g_dfd[(size_t)NPAIR * COUT];
__device__ float          g_dsq[(size_t)NPAIR * COUT];
__device__ float          g_v[(size_t)NPAIR * DTOT];            // per-point output vectors
__device__ int            g_cnt[NPAIR];
__device__ double         g_bnpart[64][COUT][2];                // phase-1 BN partials
__device__ float          g_chA[COUT];
__device__ float          g_chB[COUT];

// ---------------- cp.async helpers ----------------
__device__ __forceinline__ void cp16(void* s, const void* g) {
    unsigned int sa = (unsigned int)__cvta_generic_to_shared(s);
    asm volatile("cp.async.cg.shared.global [%0], [%1], 16;" :: "r"(sa), "l"(g));
}
#define CP_COMMIT() asm volatile("cp.async.commit_group;" ::: "memory")
#define CP_WAIT0()  asm volatile("cp.async.wait_group 0;" ::: "memory")

// ---------------- 0: transpose x -> g_xt [bm][d]; emit bf16 ----------------
__global__ void xt_kernel(const float* __restrict__ x) {
    __shared__ float t[32][33];
    int b  = blockIdx.z;
    int d0 = blockIdx.y * 32;
    int n0 = blockIdx.x * 32;
    const float* X = x + (size_t)b * DTOT * NPT;
    t[threadIdx.y][threadIdx.x] = X[(size_t)(d0 + threadIdx.y) * NPT + n0 + threadIdx.x];
    __syncthreads();
    float v = t[threadIdx.x][threadIdx.y];
    size_t o = ((size_t)(b << 11) + n0 + threadIdx.y) * DTOT + d0 + threadIdx.x;
    g_xt[o] = v;
    g_hi[o] = __float2bfloat16(v);
}

// ---------------- 1: xx in fp64 (exact) + fp32 -0.5*xx; zero counts ----------------
__global__ void xx64_kernel() {
    int p = blockIdx.x * blockDim.x + threadIdx.x;      // 16384 points
    const float* r = g_xt + (size_t)p * DTOT;
    double s = 0.0;
    #pragma unroll 8
    for (int d = 0; d < DTOT; d++) { double v = (double)r[d]; s += v * v; }
    g_xx64[p] = s;
    g_mxx[p] = (float)(-0.5 * s);
    g_cnt[p] = 0;
}

// ---------------- 2: symmetric tensor-core rank-score GEMM (upper-tri tiles + mirror) ----------------
// score[n][m] = inner(n,m) + mxx[m]   (per-row-monotone transform of pdist)
// tile (ti<=tj): primary writes rows n0-block / cols m0-block; mirror (ti<tj) writes transpose
#define SMLD 40    // bf16 smem row stride for mainloop tiles
#define SLDS 132   // float smem row stride for epilogue stage
#define KNN_SMEM (128*SLDS*4 + 1024)   // 67584 stage (unions mainloop bufs) + sxm/sxn

__global__ __launch_bounds__(256) void knn_wmma() {
    extern __shared__ char dsm[];
    __nv_bfloat16 (*sA)[128][SMLD] = reinterpret_cast<__nv_bfloat16 (*)[128][SMLD]>(dsm);
    __nv_bfloat16 (*sB)[128][SMLD] = reinterpret_cast<__nv_bfloat16 (*)[128][SMLD]>(dsm + 2 * 128 * SMLD * 2);
    float* stage = (float*)dsm;                          // unions sA/sB after mainloop
    float* sxm   = (float*)(dsm + 128 * SLDS * 4);       // mxx for cols (m-block)
    float* sxn   = sxm + 128;                            // mxx for rows (n-block)

    int bb = blockIdx.z << 11;
    // triangular decode: idx = tj*(tj+1)/2 + ti, ti <= tj
    int idx = blockIdx.x;
    int tj = (int)((sqrtf(8.0f * idx + 1.0f) - 1.0f) * 0.5f);
    while ((tj + 1) * (tj + 2) / 2 <= idx) tj++;
    while (tj * (tj + 1) / 2 > idx) tj--;
    int ti = idx - tj * (tj + 1) / 2;
    int n0 = ti * 128;      // rows
    int m0 = tj * 128;      // cols

    int tid  = threadIdx.x;
    int warp = tid >> 5;
    int wm   = warp & 1;    // 2 warps along rows, 64 each
    int wn   = warp >> 1;   // 4 warps along cols, 32 each

    // mxx slices (region above mainloop buffers: safe to load now)
    if (tid < 128) sxm[tid] = g_mxx[bb + m0 + tid];
    else           sxn[tid - 128] = g_mxx[bb + n0 + tid - 128];

    auto load_chunk = [&](int buf, int dof) {
        #pragma unroll
        for (int r = 0; r < 2; r++) {
            int s = tid + r * 256;          // 512 slots per tile
            int row = s >> 2, c8 = (s & 3) * 8;
            cp16(&sA[buf][row][c8], &g_hi[(size_t)(bb + n0 + row) * DTOT + dof + c8]);
        }
        #pragma unroll
        for (int r = 0; r < 2; r++) {
            int s = tid + r * 256;
            int row = s >> 2, c8 = (s & 3) * 8;
            cp16(&sB[buf][row][c8], &g_hi[(size_t)(bb + m0 + row) * DTOT + dof + c8]);
        }
    };

    wmma::fragment<wmma::accumulator, 16, 16, 16, float> cf[4][2];
    #pragma unroll
    for (int i = 0; i < 4; i++)
        #pragma unroll
        for (int j = 0; j < 2; j++) wmma::fill_fragment(cf[i][j], 0.0f);

    load_chunk(0, 0);
    CP_COMMIT();
    CP_WAIT0();
    __syncthreads();

    // 6 chunks of BK=32 over K=192 (pure inner product; no aug tail)
    for (int t = 0; t < 6; t++) {
        if (t < 5) { load_chunk((t + 1) & 1, (t + 1) * 32); CP_COMMIT(); }
        int cur = t & 1;
        #pragma unroll
        for (int kk = 0; kk < 32; kk += 16) {
            wmma::fragment<wmma::matrix_a, 16, 16, 16, __nv_bfloat16, wmma::row_major> af[4];
            wmma::fragment<wmma::matrix_b, 16, 16, 16, __nv_bfloat16, wmma::col_major> bfr[2];
            #pragma unroll
            for (int i = 0; i < 4; i++)
                wmma::load_matrix_sync(af[i], &sA[cur][wm * 64 + i * 16][kk], SMLD);
            #pragma unroll
            for (int j = 0; j < 2; j++)
                wmma::load_matrix_sync(bfr[j], &sB[cur][wn * 32 + j * 16][kk], SMLD);
            #pragma unroll
            for (int i = 0; i < 4; i++)
                #pragma unroll
                for (int j = 0; j < 2; j++)
                    wmma::mma_sync(cf[i][j], af[i], bfr[j], cf[i][j]);
        }
        if (t < 5) CP_WAIT0();
        __syncthreads();
    }

    // stage pure inner tile in smem (reuses mainloop buffers; all reads done)
    #pragma unroll
    for (int i = 0; i < 4; i++)
        #pragma unroll
        for (int j = 0; j < 2; j++)
            wmma::store_matrix_sync(&stage[(wm * 64 + i * 16) * SLDS + wn * 32 + j * 16],
                                    cf[i][j], SLDS, wmma::mem_row_major);
    __syncthreads();

    int row  = tid >> 1;
    int half = tid & 1;

    // primary: score[n0+row][m0+c] = stage[row][c] + mxx[m0+c]
    {
        const float* srow = stage + row * SLDS + half * 64;
        const float* xm   = sxm + half * 64;
        float* orow = g_pdist + (size_t)(bb + n0 + row) * NPT + m0 + half * 64;
        #pragma unroll
        for (int g = 0; g < 2; g++) {
            float gm = -INFINITY;
            #pragma unroll
            for (int c0 = 0; c0 < 32; c0 += 4) {
                float4 v = *(const float4*)&srow[g * 32 + c0];
                v.x += xm[g * 32 + c0 + 0];
                v.y += xm[g * 32 + c0 + 1];
                v.z += xm[g * 32 + c0 + 2];
                v.w += xm[g * 32 + c0 + 3];
                gm = fmaxf(gm, fmaxf(fmaxf(v.x, v.y), fmaxf(v.z, v.w)));
                *(float4*)&orow[g * 32 + c0] = v;
            }
            g_rtm[(size_t)(bb + n0 + row) * NGRP + tj * 4 + half * 2 + g] = gm;
        }
    }

    // mirror (ti < tj): score[m0+row][n0+c] = stage[c][row] + mxx[n0+c]
    if (ti != tj) {
        float* orow = g_pdist + (size_t)(bb + m0 + row) * NPT + n0 + half * 64;
        #pragma unroll
        for (int g = 0; g < 2; g++) {
            int nb = half * 64 + g * 32;
            float gm = -INFINITY;
            #pragma unroll
            for (int c0 = 0; c0 < 32; c0 += 4) {
                float4 v;
                v.x = stage[(nb + c0 + 0) * SLDS + row] + sxn[nb + c0 + 0];
                v.y = stage[(nb + c0 + 1) * SLDS + row] + sxn[nb + c0 + 1];
                v.z = stage[(nb + c0 + 2) * SLDS + row] + sxn[nb + c0 + 2];
                v.w = stage[(nb + c0 + 3) * SLDS + row] + sxn[nb + c0 + 3];
                gm = fmaxf(gm, fmaxf(fmaxf(v.x, v.y), fmaxf(v.z, v.w)));
                *(float4*)&orow[g * 32 + c0] = v;
            }
            g_rtm[(size_t)(bb + m0 + row) * NGRP + ti * 4 + half * 2 + g] = gm;
        }
    }
}

// ---------------- 3: group-skip threshold-collect top-TCAND per row (warp per row) ----------------
__global__ __launch_bounds__(256) void cand_kernel() {
    int gwarp = (blockIdx.x * blockDim.x + threadIdx.x) >> 5;   // row id [0,16384)
    int lane  = threadIdx.x & 31;
    int wl    = threadIdx.x >> 5;

    __shared__ float s_v[8][CCAP];
    __shared__ int   s_i[8][CCAP];
    __shared__ int   s_g[8][NGRP];

    // load 64 group maxima (2 per lane)
    const float* rtm = g_rtm + (size_t)gwarp * NGRP;
    float gm0 = rtm[lane];
    float gm1 = rtm[lane + 32];

    // tau = 16th-largest of the 64 group maxima
    float a0 = gm0, a1 = gm1, tau = 0.f;
    #pragma unroll
    for (int r = 0; r < 16; r++) {
        float mx = fmaxf(a0, a1);
        #pragma unroll
        for (int off = 16; off; off >>= 1) mx = fmaxf(mx, __shfl_xor_sync(0xffffffff, mx, off));
        tau = mx;
        unsigned msk = __ballot_sync(0xffffffff, a0 == mx || a1 == mx);
        int src = __ffs(msk) - 1;
        if (lane == src) { if (a0 == mx) a0 = -INFINITY; else a1 = -INFINITY; }
    }

    // compact list of selected groups (max >= tau)
    unsigned m0s = __ballot_sync(0xffffffff, gm0 >= tau);
    unsigned m1s = __ballot_sync(0xffffffff, gm1 >= tau);
    unsigned lt = (1u << lane) - 1;
    int n0s = __popc(m0s);
    if (gm0 >= tau) s_g[wl][__popc(m0s & lt)] = lane;
    if (gm1 >= tau) s_g[wl][n0s + __popc(m1s & lt)] = 32 + lane;
    int nsel = n0s + __popc(m1s);
    __syncwarp();

    // scan only selected groups
    const float4* row4 = (const float4*)(g_pdist + (size_t)gwarp * NPT);
    int base = 0;
    for (int c = 0; c < nsel; c += 4) {
        int gi  = c + (lane >> 3);
        int sub = lane & 7;
        bool act = gi < nsel;
        int grp = act ? s_g[wl][gi] : 0;
        int q = grp * 8 + sub;
        float4 v = act ? row4[q] : make_float4(-INFINITY, -INFINITY, -INFINITY, -INFINITY);
        float vals[4] = {v.x, v.y, v.z, v.w};
        float mx = fmaxf(fmaxf(vals[0], vals[1]), fmaxf(vals[2], vals[3]));
        unsigned any = __ballot_sync(0xffffffff, mx >= tau);
        if (any) {
            #pragma unroll
            for (int e = 0; e < 4; e++) {
                bool hit = vals[e] >= tau;
                unsigned m = __ballot_sync(0xffffffff, hit);
                if (m) {
                    if (hit) {
                        int pos = base + __popc(m & lt);
                        if (pos < CCAP) { s_v[wl][pos] = vals[e]; s_i[wl][pos] = q * 4 + e; }
                    }
                    base += __popc(m);
                }
            }
        }
    }
    int cnt = min(base, CCAP);
    __syncwarp();

    int* out = g_cand + (size_t)gwarp * TCAND;
    if (cnt <= 128) {
        float rv[4]; int ri[4];
        #pragma unroll
        for (int j = 0; j < 4; j++) {
            int idx = lane + 32 * j;
            bool a = idx < cnt;
            rv[j] = a ? s_v[wl][idx] : -INFINITY;
            ri[j] = a ? s_i[wl][idx] : 0x7fffffff;
        }
        for (int r = 0; r < TCAND; r++) {
            float bv = -INFINITY; int bi = 0x7fffffff;
            #pragma unroll
            for (int j = 0; j < 4; j++)
                if (rv[j] > bv || (rv[j] == bv && ri[j] < bi)) { bv = rv[j]; bi = ri[j]; }
            #pragma unroll
            for (int off = 16; off; off >>= 1) {
                float ov = __shfl_down_sync(0xffffffff, bv, off);
                int   oi = __shfl_down_sync(0xffffffff, bi, off);
                if (ov > bv || (ov == bv && oi < bi)) { bv = ov; bi = oi; }
            }
            bi = __shfl_sync(0xffffffff, bi, 0);
            if (lane == 0) out[r] = bi;
            #pragma unroll
            for (int j = 0; j < 4; j++)
                if (ri[j] == bi) rv[j] = -INFINITY;
        }
    } else {
        for (int r = 0; r < TCAND; r++) {
            float bv = -INFINITY; int bi = 0x7fffffff;
            for (int t = lane; t < cnt; t += 32) {
                float vv = s_v[wl][t]; int ii = s_i[wl][t];
                if (vv > bv || (vv == bv && ii < bi)) { bv = vv; bi = ii; }
            }
            #pragma unroll
            for (int off = 16; off; off >>= 1) {
                float ov = __shfl_down_sync(0xffffffff, bv, off);
                int   oi = __shfl_down_sync(0xffffffff, bi, off);
                if (ov > bv || (ov == bv && oi < bi)) { bv = ov; bi = oi; }
            }
            bv = __shfl_sync(0xffffffff, bv, 0);
            bi = __shfl_sync(0xffffffff, bi, 0);
            if (lane == 0) out[r] = bi;
            for (int t = lane; t < cnt; t += 32)
                if (s_i[wl][t] == bi) s_v[wl][t] = -INFINITY;
            __syncwarp();
        }
    }
}

// ---------------- 4: compensated-fp32 (Dot2) refine -> final top-KNN (+ fused counts) ----------------
__global__ __launch_bounds__(256) void refine_kernel() {
    int row  = (blockIdx.x * blockDim.x + threadIdx.x) >> 5;  // [0,16384)
    int lane = threadIdx.x & 31;
    int wl   = threadIdx.x >> 5;
    int b    = row >> 11;

    __shared__ float s_val[8][TCAND];
    __shared__ int   s_id[8][TCAND];

    float xn[6];
    #pragma unroll
    for (int u = 0; u < 6; u++) xn[u] = g_xt[(size_t)row * DTOT + lane + 32 * u];
    float xxn = (float)g_xx64[row];

    for (int j = 0; j < TCAND; j++) {
        int m = g_cand[(size_t)row * TCAND + j];
        const float* xm = g_xt + ((size_t)(b << 11) + m) * DTOT;
        float s = 0.0f, comp = 0.0f;
        #pragma unroll
        for (int u = 0; u < 6; u++) {
            float a = xn[u], bv = xm[lane + 32 * u];
            float p  = __fmul_rn(a, bv);
            float pe = __fmaf_rn(a, bv, -p);              // exact product error
            float t  = __fadd_rn(s, p);                   // Knuth TwoSum
            float z  = __fsub_rn(t, s);
            float e  = __fadd_rn(__fsub_rn(s, __fsub_rn(t, z)), __fsub_rn(p, z));
            s = t;
            comp = __fadd_rn(comp, __fadd_rn(e, pe));
        }
        #pragma unroll
        for (int off = 16; off; off >>= 1) {
            float os = __shfl_down_sync(0xffffffff, s,    off);
            float oc = __shfl_down_sync(0xffffffff, comp, off);
            float t  = __fadd_rn(s, os);
            float z  = __fsub_rn(t, s);
            float e  = __fadd_rn(__fsub_rn(s, __fsub_rn(t, z)), __fsub_rn(os, z));
            s = t;
            comp = __fadd_rn(comp, __fadd_rn(e, oc));
        }
        if (lane == 0) {
            float innerf = __fadd_rn(s, comp);
            float pf = 2.0f * innerf;
            pf = pf - xxn;
            pf = pf - (float)g_xx64[(size_t)(b << 11) + m];
            s_val[wl][j] = pf;
            s_id[wl][j]  = m;
        }
    }
    __syncwarp();

    if (lane == 0) {
        int* out = g_idx + (size_t)row * KNN;
        int bb = (row >> 11) << 11;
        for (int r = 0; r < KNN; r++) {
            float bv = -INFINITY; int bi = 0x7fffffff; int bs = 0;
            #pragma unroll
            for (int t = 0; t < TCAND; t++) {
                float v = s_val[wl][t]; int id = s_id[wl][t];
                if (v > bv || (v == bv && id < bi)) { bv = v; bi = id; bs = t; }
            }
            out[r] = bi;
            atomicAdd(&g_cnt[bb + bi], 1);
            s_val[wl][bs] = -INFINITY;
        }
    }
}

// ---------------- 5: y_feat / y_dir [bm][od]  + fused per-point stats ----------------
__global__ void feat_kernel(const float* __restrict__ x,
                            const float* __restrict__ Wf,
                            const float* __restrict__ Wd) {
    __shared__ float wfs[64][64];   // [c][o]; reused as sf stage after compute
    __shared__ float wds[64][64];   //          reused as sd stage
    __shared__ float xs[DTOT][16];

    int b = blockIdx.y;
    int n0 = blockIdx.x * 16;
    int tid = threadIdx.x;          // 192

    for (int i = tid; i < 4096; i += 192) {
        int o = i >> 6, c = i & 63;
        wfs[c][o] = Wf[i];
        wds[c][o] = Wd[i];
    }
    const float* X = x + (size_t)b * DTOT * NPT;
    for (int i = tid; i < DTOT * 16; i += 192) {
        int c3 = i >> 4, n = i & 15;
        xs[c3][n] = X[(size_t)c3 * NPT + n0 + n];
    }
    __syncthreads();

    int o = tid / 3;
    int d = tid - 3 * o;

    float af[16], ad_[16];
    #pragma unroll
    for (int n = 0; n < 16; n++) { af[n] = 0.f; ad_[n] = 0.f; }

    for (int c = 0; c < 64; c++) {
        float wf = wfs[c][o], wd = wds[c][o];
        #pragma unroll
        for (int n = 0; n < 16; n++) {
            float xv = xs[c * 3 + d][n];
            af[n]  = fmaf(wf, xv, af[n]);
            ad_[n] = fmaf(wd, xv, ad_[n]);
        }
    }
    #pragma unroll
    for (int n = 0; n < 16; n++) {
        size_t base = ((size_t)b * NPT + n0 + n) * DTOT + tid;
        g_yf[base] = af[n];
        g_yd[base] = ad_[n];
    }

    // fused pstat: stage af/ad_ into reused smem (pad 17, conflict-free), compute stats
    __syncthreads();
    float* sf = &wfs[0][0];
    float* sd = &wds[0][0];
    #pragma unroll
    for (int n = 0; n < 16; n++) {
        sf[tid * 17 + n] = af[n];
        sd[tid * 17 + n] = ad_[n];
    }
    __syncthreads();
    for (int i = tid; i < 1024; i += 192) {
        int n = i >> 6, oo = i & 63;
        float f0 = sf[(oo * 3 + 0) * 17 + n];
        float f1 = sf[(oo * 3 + 1) * 17 + n];
        float f2 = sf[(oo * 3 + 2) * 17 + n];
        float g0 = sd[(oo * 3 + 0) * 17 + n];
        float g1 = sd[(oo * 3 + 1) * 17 + n];
        float g2 = sd[(oo * 3 + 2) * 17 + n];
        size_t t = ((size_t)b * NPT + n0 + n) * COUT + oo;
        g_nrm[t] = sqrtf(f0 * f0 + f1 * f1 + f2 * f2);
        g_dfd[t] = f0 * g0 + f1 * g1 + f2 * g2;
        g_dsq[t] = g0 * g0 + g1 * g1 + g2 * g2;
    }
}

// ---------------- 8a: BN stats phase 1 — coalesced count-weighted partials ----------------
__global__ void bnpart_kernel() {
    int p = blockIdx.x;      // 64 blocks, each covers 256 bm
    int t = threadIdx.x;     // 256
    int g = t >> 6, o = t & 63;
    double s1 = 0.0, s2 = 0.0;
    for (int i = 0; i < 64; i++) {
        int bm = p * 256 + g + 4 * i;
        float v = g_nrm[(size_t)bm * COUT + o];
        double c = (double)g_cnt[bm];
        s1 += c * v;
        s2 += c * (double)v * (double)v;
    }
    __shared__ double r1[256], r2[256];
    r1[t] = s1; r2[t] = s2;
    __syncthreads();
    if (t < 64) {
        g_bnpart[p][t][0] = r1[t] + r1[t + 64] + r1[t + 128] + r1[t + 192];
        g_bnpart[p][t][1] = r2[t] + r2[t + 64] + r2[t + 128] + r2[t + 192];
    }
}

// ---------------- 8b: BN stats phase 2 — final reduce -> chA/chB ----------------
__global__ void bnfinal_kernel(const float* __restrict__ gamma, const float* __restrict__ beta) {
    int o = threadIdx.x;     // 64
    double s1 = 0.0, s2 = 0.0;
    for (int p = 0; p < 64; p++) {
        s1 += g_bnpart[p][o][0];
        s2 += g_bnpart[p][o][1];
    }
    const double cnt = (double)NEDGE;
    double mean = s1 / cnt;
    double var  = s2 / cnt - mean * mean;
    double a = (double)gamma[o] / sqrt(var + (double)BN_EPS);
    g_chA[o] = (float)a;
    g_chB[o] = (float)((double)beta[o] - mean * a);
}

// ---------------- 9: per-point output vectors v ----------------
__global__ void v_kernel() {
    int bm = blockIdx.x;
    int od = threadIdx.x;       // 192
    int o = od / 3;
    size_t t = (size_t)bm * DTOT + od;
    size_t s = (size_t)bm * COUT + o;
    float n    = g_nrm[s];
    float scale = g_chA[o] + g_chB[o] / n;     // norm_bn / norm
    float dot  = scale * g_dfd[s];
    float pv   = scale * g_yf[t];
    float outv = pv;
    if (dot < 0.f) outv = pv - dot / (g_dsq[s] + VN_EPS) * g_yd[t];
    g_v[t] = outv;
}

// ---------------- 10: gather-mean to output ----------------
__global__ void gather_kernel(float* __restrict__ out) {
    __shared__ int sidx[16 * KNN];
    int b  = blockIdx.y;
    int n0 = blockIdx.x * 16;
    int tid = threadIdx.x;      // 192
    if (tid < 16 * KNN) sidx[tid] = g_idx[((size_t)b * NPT + n0) * KNN + tid];
    __syncthreads();

    const float* vb = g_v + (size_t)b * NPT * DTOT;
    float res[16];
    #pragma unroll
    for (int n = 0; n < 16; n++) {
        float acc = 0.f;
        #pragma unroll
        for (int k = 0; k < KNN; k++) {
            int m = sidx[n * KNN + k];
            acc += vb[(size_t)m * DTOT + tid];
        }
        res[n] = acc * (1.0f / (float)KNN);
    }
    float* ob = out + ((size_t)b * DTOT + tid) * NPT + n0;
    *(float4*)(ob)      = make_float4(res[0],  res[1],  res[2],  res[3]);
    *(float4*)(ob + 4)  = make_float4(res[4],  res[5],  res[6],  res[7]);
    *(float4*)(ob + 8)  = make_float4(res[8],  res[9],  res[10], res[11]);
    *(float4*)(ob + 12) = make_float4(res[12], res[13], res[14], res[15]);
}

// ---------------- launch ----------------
extern "C" void kernel_launch(void* const* d_in, const int* in_sizes, int n_in,
                              void* d_out, int out_size) {
    const float* x     = (const float*)d_in[0];
    const float* Wf    = (const float*)d_in[1];
    const float* Wd    = (const float*)d_in[2];
    const float* gamma = (const float*)d_in[3];
    const float* beta  = (const float*)d_in[4];
    float* out = (float*)d_out;

    cudaFuncSetAttribute(knn_wmma, cudaFuncAttributeMaxDynamicSharedMemorySize, KNN_SMEM);

    xt_kernel<<<dim3(NPT / 32, DTOT / 32, BATCH), dim3(32, 32)>>>(x);
    xx64_kernel<<<NPAIR / 256, 256>>>();
    knn_wmma<<<dim3(NPAIRS_TRI, 1, BATCH), 256, KNN_SMEM>>>();
    cand_kernel<<<NPAIR / 8, 256>>>();
    refine_kernel<<<NPAIR / 8, 256>>>();
    feat_kernel<<<dim3(NPT / 16, BATCH), 192>>>(x, Wf, Wd);
    bnpart_kernel<<<64, 256>>>();
    bnfinal_kernel<<<1, 64>>>(gamma, beta);
    v_kernel<<<NPAIR, DTOT>>>();
    gather_kernel<<<dim3(NPT / 16, BATCH), DTOT>>>(out);
}